// round 9
// baseline (speedup 1.0000x reference)
#include <cuda_runtime.h>
#include <math.h>

// ---------------- problem constants ----------------
#define BB   8
#define NN   4096
#define KNB  20
#define NKK  (NN*KNB)
#define EPSV 1e-6f
#define BNEPS 1e-5f

// ---------------- static device scratch (allocation-free) ----------------
__device__ float  g_bufP[BB*341*3*NN];
__device__ float  g_bufD[BB*341*3*NN];
__device__ int    g_idx [BB*NKK];
__device__ float  g_h   [BB*21*3*NN];
__device__ float  g_h1  [BB*21*3*NN];
__device__ float  g_s1  [BB*21*3*NN];
__device__ float  g_s2  [BB*42*3*NN];
__device__ float  g_s3  [BB*341*3*NN];
__device__ float  g_sp  [BB*341*3];
__device__ float  g_t1  [BB*170*3];
__device__ float  g_t2  [BB*85*3];
__device__ float  g_t3  [BB*21*3];
__device__ float  g_h42 [BB*42*3*NN];
__device__ float  g_h42b[BB*42*3*NN];
__device__ float  g_mean3[BB*341*3];
__device__ float  g_h682[BB*682*3*NN];
__device__ float  g_z1  [BB*341*3*NN];
__device__ float  g_z0s [BB*3*3*NN];
__device__ float  g_part[682*64];
__device__ float  g_bn  [682*2];
__device__ double g_partd[21*64*2];
__device__ float  g_bnpos[21*2];   // stage-1: [mean, denom=sqrt(var+eps)] as f32

// ---------------- kNN: fp64-truth keys -----------------------------------------
__global__ void knn_kernel(const float* __restrict__ x, int* __restrict__ idxout) {
    __shared__ float sx0[NN], sx1[NN], sx2[NN];
    int b = blockIdx.y;
    for (int t = threadIdx.x; t < 3*NN; t += blockDim.x) {
        float v = x[(size_t)b*3*NN + t];
        int d = t / NN, n = t - d*NN;
        if (d == 0) sx0[n] = v; else if (d == 1) sx1[n] = v; else sx2[n] = v;
    }
    __syncthreads();
    int i = blockIdx.x * blockDim.x + threadIdx.x;
    double xi0 = (double)sx0[i], xi1 = (double)sx1[i], xi2 = (double)sx2[i];
    double xxi = xi0*xi0 + xi1*xi1 + xi2*xi2;

    double bv[KNB]; int bi[KNB];
    #pragma unroll
    for (int t = 0; t < KNB; t++) { bv[t] = -1.0e300; bi[t] = 0; }
    double minv = -1.0e300; int minp = 0;

    for (int j = 0; j < NN; j++) {
        double a0 = (double)sx0[j], a1 = (double)sx1[j], a2 = (double)sx2[j];
        double dot = xi0*a0 + xi1*a1 + xi2*a2;
        double pd  = 2.0*dot - xxi - (a0*a0 + a1*a1 + a2*a2);
        if (pd > minv) {
            bv[minp] = pd; bi[minp] = j;
            minv = bv[0]; minp = 0;
            #pragma unroll
            for (int t = 1; t < KNB; t++)
                if (bv[t] < minv) { minv = bv[t]; minp = t; }
        }
    }
    int* dst = idxout + ((size_t)b*NN + i)*KNB;
    #pragma unroll
    for (int t = 0; t < KNB; t++) dst[t] = bi[t];
}

// ---- XLA-replica f32 feature build: e=xj-xi, xi, cross(xj,xi), no fma ----------
__device__ __forceinline__ void feat_f32(const float* __restrict__ xb, int n, int j,
                                         float* f) {
    float xi0 = xb[n],  xi1 = xb[NN + n],  xi2 = xb[2*NN + n];
    float xj0 = xb[j],  xj1 = xb[NN + j],  xj2 = xb[2*NN + j];
    f[0] = __fsub_rn(xj0, xi0); f[1] = __fsub_rn(xj1, xi1); f[2] = __fsub_rn(xj2, xi2);
    f[3] = xi0; f[4] = xi1; f[5] = xi2;
    f[6] = __fsub_rn(__fmul_rn(xj1, xi2), __fmul_rn(xj2, xi1));
    f[7] = __fsub_rn(__fmul_rn(xj2, xi0), __fmul_rn(xj0, xi2));
    f[8] = __fsub_rn(__fmul_rn(xj0, xi1), __fmul_rn(xj1, xi0));
}

// ascending fma chain from 0 over 3 channels (XLA dot order)
__device__ __forceinline__ float dot3_fma(float w0, float w1, float w2,
                                          float f0, float f1, float f2) {
    float a = __fmul_rn(w0, f0);
    a = __fmaf_rn(w1, f1, a);
    a = __fmaf_rn(w2, f2, a);
    return a;
}

// sum of 3 products, mul then left-assoc adds (XLA reduce of multiply — no fma)
__device__ __forceinline__ float sum3_nofma(float a0, float b0, float a1, float b1,
                                            float a2, float b2) {
    return __fadd_rn(__fadd_rn(__fmul_rn(a0, b0), __fmul_rn(a1, b1)), __fmul_rn(a2, b2));
}

// ---------------- stage-1 BN stats from replica-f32 norms (fp64 accumulate) -----
__global__ void bn_stats_pos(const float* __restrict__ x, const int* __restrict__ idx,
                             const float* __restrict__ Wf, int nblk, int pass,
                             const float* __restrict__ bnpos_in,
                             double* __restrict__ part) {
    int o = blockIdx.x, blk = blockIdx.y;
    float w0 = Wf[o*3], w1 = Wf[o*3+1], w2 = Wf[o*3+2];
    float mean = (pass == 1) ? bnpos_in[o] : 0.f;
    double s = 0.0;
    const int total = BB*NKK;
    for (int t = blk*blockDim.x + threadIdx.x; t < total; t += nblk*blockDim.x) {
        int b = t / NKK, nk = t - (t / NKK)*NKK;
        int n = nk / KNB;
        int j = idx[(size_t)b*NKK + nk];
        const float* xb = x + (size_t)b*3*NN;
        float f[9]; feat_f32(xb, n, j, f);
        float p0 = dot3_fma(w0, w1, w2, f[0], f[3], f[6]);
        float p1 = dot3_fma(w0, w1, w2, f[1], f[4], f[7]);
        float p2 = dot3_fma(w0, w1, w2, f[2], f[5], f[8]);
        float nsq = sum3_nofma(p0, p0, p1, p1, p2, p2);
        float nr = __fadd_rn(__fsqrt_rn(nsq), EPSV);
        if (pass == 0) s += (double)nr;
        else { double d = (double)__fsub_rn(nr, mean); s += d*d; }
    }
    __shared__ double sh[256];
    sh[threadIdx.x] = s;
    __syncthreads();
    for (int st = 128; st > 0; st >>= 1) {
        if (threadIdx.x < st) sh[threadIdx.x] += sh[threadIdx.x+st];
        __syncthreads();
    }
    if (threadIdx.x == 0) part[(size_t)o*nblk + blk] = sh[0];
}

__global__ void bn_pos_final(const double* __restrict__ part, float* __restrict__ bnpos,
                             int nblk, int cnt, int pass) {
    int o = blockIdx.x;
    __shared__ double s1[64];
    double a = 0.0;
    for (int t = threadIdx.x; t < nblk; t += 64) a += part[(size_t)o*nblk + t];
    s1[threadIdx.x] = a;
    __syncthreads();
    for (int st = 32; st > 0; st >>= 1) {
        if (threadIdx.x < st) s1[threadIdx.x] += s1[threadIdx.x+st];
        __syncthreads();
    }
    if (threadIdx.x == 0) {
        if (pass == 0) bnpos[o] = (float)(s1[0] / cnt);
        else {
            float var = (float)(s1[0] / cnt);
            bnpos[21 + o] = __fsqrt_rn(__fadd_rn(var, BNEPS));
        }
    }
}

// ------- stage-1 XLA-replica f32: feature+linear+BN+lrelu, fp64-free pool -------
__global__ void pool_k_replica(const float* __restrict__ x, const int* __restrict__ idx,
                               const float* __restrict__ Wf, const float* __restrict__ Wd,
                               const float* __restrict__ bnpos,
                               const float* __restrict__ poolWd,
                               float* __restrict__ OutH) {
    int bnid = blockIdx.x; int b = bnid / NN; int n = bnid - b*NN;
    __shared__ float hs[21][3][KNB];
    __shared__ float wpool[441];
    __shared__ float wf[63], wd[63], bns[42];
    int lane = threadIdx.x;
    for (int t = lane; t < 441; t += 32) wpool[t] = poolWd[t];
    for (int t = lane; t < 63; t += 32) { wf[t] = Wf[t]; wd[t] = Wd[t]; }
    for (int t = lane; t < 42; t += 32) bns[t] = bnpos[t];
    __syncthreads();

    if (lane < KNB) {
        int k = lane;
        int j = idx[(size_t)b*NKK + (size_t)n*KNB + k];
        const float* xb = x + (size_t)b*3*NN;
        float f[9]; feat_f32(xb, n, j, f);
        for (int o = 0; o < 21; o++) {
            float a0 = wf[o*3], a1 = wf[o*3+1], a2 = wf[o*3+2];
            float p0 = dot3_fma(a0, a1, a2, f[0], f[3], f[6]);
            float p1 = dot3_fma(a0, a1, a2, f[1], f[4], f[7]);
            float p2 = dot3_fma(a0, a1, a2, f[2], f[5], f[8]);
            float nsq = sum3_nofma(p0, p0, p1, p1, p2, p2);
            float nr = __fadd_rn(__fsqrt_rn(nsq), EPSV);
            // norm_bn = (nr - mean) / sqrt(var + eps)
            float nbn = __fdiv_rn(__fsub_rn(nr, bns[o]), bns[21 + o]);
            // p' = (p / nr) * norm_bn   (reference op order: div then mul)
            float q0 = __fmul_rn(__fdiv_rn(p0, nr), nbn);
            float q1 = __fmul_rn(__fdiv_rn(p1, nr), nbn);
            float q2 = __fmul_rn(__fdiv_rn(p2, nr), nbn);
            float c0 = wd[o*3], c1 = wd[o*3+1], c2 = wd[o*3+2];
            float d0 = dot3_fma(c0, c1, c2, f[0], f[3], f[6]);
            float d1 = dot3_fma(c0, c1, c2, f[1], f[4], f[7]);
            float d2 = dot3_fma(c0, c1, c2, f[2], f[5], f[8]);
            float dotv = sum3_nofma(q0, d0, q1, d1, q2, d2);
            float dsq  = sum3_nofma(d0, d0, d1, d1, d2, d2);
            if (!(dotv >= 0.f)) {
                float coef = __fdiv_rn(dotv, __fadd_rn(dsq, EPSV));
                q0 = __fsub_rn(q0, __fmul_rn(coef, d0));
                q1 = __fsub_rn(q1, __fmul_rn(coef, d1));
                q2 = __fsub_rn(q2, __fmul_rn(coef, d2));
            }
            hs[o][0][k] = q0; hs[o][1][k] = q1; hs[o][2][k] = q2;
        }
    }
    __syncthreads();
    if (lane < 21) {
        int o = lane;
        float bestdot = -3.0e38f; int bestk = 0;
        for (int k = 0; k < KNB; k++) {
            // d_o,v = ascending fma chain over 21 channels (cublas order)
            float d0 = __fmul_rn(wpool[o*21], hs[0][0][k]);
            float d1 = __fmul_rn(wpool[o*21], hs[0][1][k]);
            float d2 = __fmul_rn(wpool[o*21], hs[0][2][k]);
            for (int c = 1; c < 21; c++) {
                float w = wpool[o*21 + c];
                d0 = __fmaf_rn(w, hs[c][0][k], d0);
                d1 = __fmaf_rn(w, hs[c][1][k], d1);
                d2 = __fmaf_rn(w, hs[c][2][k], d2);
            }
            float dotv = sum3_nofma(hs[o][0][k], d0, hs[o][1][k], d1, hs[o][2][k], d2);
            if (dotv > bestdot) { bestdot = dotv; bestk = k; }   // first-max wins
        }
        #pragma unroll
        for (int v = 0; v < 3; v++)
            OutH[((size_t)(b*21 + o)*3 + v)*NN + n] = hs[o][v][bestk];
    }
}

// Kahan fold
#define KAHAN_ADD(acc, comp, val) do { \
    float _y = (val) - (comp);         \
    float _t = (acc) + _y;             \
    (comp) = (_t - (acc)) - _y;        \
    (acc) = _t;                        \
} while (0)

// ---------------- generic channel GEMM ------------------------------------------
__global__ void gemm_vn(const float* __restrict__ W, const float* __restrict__ X,
                        float* __restrict__ Y, int O, int C, int J) {
    const float* Xb = X + (size_t)blockIdx.z * C * J;
    float*       Yb = Y + (size_t)blockIdx.z * O * J;
    int row0 = blockIdx.y * 64;
    int col0 = blockIdx.x * 64;
    __shared__ float Ws[16][68];
    __shared__ float Xs[16][68];
    int tid = threadIdx.x;
    int tx = tid % 16, ty = tid / 16;
    float acc[4][4] = {};
    float cmp[4][4] = {};

    for (int k0 = 0; k0 < C; k0 += 16) {
        {
            int c = tid % 16, r4 = tid / 16;
            #pragma unroll
            for (int q = 0; q < 4; q++) {
                int r = r4 + q*16; int o = row0 + r; int cc = k0 + c;
                Ws[c][r] = (o < O && cc < C) ? W[(size_t)o*C + cc] : 0.f;
            }
        }
        {
            int jl = tid % 64, k4 = tid / 64;
            #pragma unroll
            for (int q = 0; q < 4; q++) {
                int kk = k4 + q*4; int cc = k0 + kk; int col = col0 + jl;
                Xs[kk][jl] = (cc < C && col < J) ? Xb[(size_t)cc*J + col] : 0.f;
            }
        }
        __syncthreads();
        float cacc[4][4] = {};
        #pragma unroll
        for (int kk = 0; kk < 16; kk++) {
            float wr[4], xr[4];
            #pragma unroll
            for (int q = 0; q < 4; q++) wr[q] = Ws[kk][ty*4+q];
            #pragma unroll
            for (int q = 0; q < 4; q++) xr[q] = Xs[kk][tx*4+q];
            #pragma unroll
            for (int a = 0; a < 4; a++)
                #pragma unroll
                for (int bq = 0; bq < 4; bq++)
                    cacc[a][bq] += wr[a]*xr[bq];
        }
        #pragma unroll
        for (int a = 0; a < 4; a++)
            #pragma unroll
            for (int bq = 0; bq < 4; bq++)
                KAHAN_ADD(acc[a][bq], cmp[a][bq], cacc[a][bq]);
        __syncthreads();
    }
    #pragma unroll
    for (int a = 0; a < 4; a++) {
        int o = row0 + ty*4 + a;
        if (o < O) {
            #pragma unroll
            for (int bq = 0; bq < 4; bq++) {
                int col = col0 + tx*4 + bq;
                if (col < J) Yb[(size_t)o*J + col] = acc[a][bq];
            }
        }
    }
}

// ---------------- fused dual GEMM ----------------------------------------------
__global__ void gemm_vn2(const float* __restrict__ Wf, const float* __restrict__ Wd,
                         const float* __restrict__ X,
                         float* __restrict__ P, float* __restrict__ D,
                         int O, int C, int J) {
    const float* Xb = X + (size_t)blockIdx.z * C * J;
    float*       Pb = P + (size_t)blockIdx.z * O * J;
    float*       Db = D + (size_t)blockIdx.z * O * J;
    int row0 = blockIdx.y * 64;
    int col0 = blockIdx.x * 64;
    __shared__ float Wfs[16][68];
    __shared__ float Wds[16][68];
    __shared__ float Xs [16][68];
    int tid = threadIdx.x;
    int tx = tid % 16, ty = tid / 16;
    float accP[4][4] = {};
    float cmpP[4][4] = {};
    float accD[4][4] = {};
    float cmpD[4][4] = {};

    for (int k0 = 0; k0 < C; k0 += 16) {
        {
            int c = tid % 16, r4 = tid / 16;
            #pragma unroll
            for (int q = 0; q < 4; q++) {
                int r = r4 + q*16; int o = row0 + r; int cc = k0 + c;
                bool ok = (o < O && cc < C);
                Wfs[c][r] = ok ? Wf[(size_t)o*C + cc] : 0.f;
                Wds[c][r] = ok ? Wd[(size_t)o*C + cc] : 0.f;
            }
        }
        {
            int jl = tid % 64, k4 = tid / 64;
            #pragma unroll
            for (int q = 0; q < 4; q++) {
                int kk = k4 + q*4; int cc = k0 + kk; int col = col0 + jl;
                Xs[kk][jl] = (cc < C && col < J) ? Xb[(size_t)cc*J + col] : 0.f;
            }
        }
        __syncthreads();
        float caccP[4][4] = {};
        float caccD[4][4] = {};
        #pragma unroll
        for (int kk = 0; kk < 16; kk++) {
            float wfr[4], wdr[4], xr[4];
            #pragma unroll
            for (int q = 0; q < 4; q++) wfr[q] = Wfs[kk][ty*4+q];
            #pragma unroll
            for (int q = 0; q < 4; q++) wdr[q] = Wds[kk][ty*4+q];
            #pragma unroll
            for (int q = 0; q < 4; q++) xr[q]  = Xs[kk][tx*4+q];
            #pragma unroll
            for (int a = 0; a < 4; a++)
                #pragma unroll
                for (int bq = 0; bq < 4; bq++) {
                    caccP[a][bq] += wfr[a]*xr[bq];
                    caccD[a][bq] += wdr[a]*xr[bq];
                }
        }
        #pragma unroll
        for (int a = 0; a < 4; a++)
            #pragma unroll
            for (int bq = 0; bq < 4; bq++) {
                KAHAN_ADD(accP[a][bq], cmpP[a][bq], caccP[a][bq]);
                KAHAN_ADD(accD[a][bq], cmpD[a][bq], caccD[a][bq]);
            }
        __syncthreads();
    }
    #pragma unroll
    for (int a = 0; a < 4; a++) {
        int o = row0 + ty*4 + a;
        if (o < O) {
            #pragma unroll
            for (int bq = 0; bq < 4; bq++) {
                int col = col0 + tx*4 + bq;
                if (col < J) {
                    Pb[(size_t)o*J + col] = accP[a][bq];
                    Db[(size_t)o*J + col] = accD[a][bq];
                }
            }
        }
    }
}

// ---------------- BN stats: two-pass f32 ----------------------------------------
__global__ void bn_mean_partial(const float* __restrict__ Y, int O, int M, int BMtot,
                                int nblk, float* __restrict__ part) {
    int o = blockIdx.x, blk = blockIdx.y;
    float s = 0.f;
    for (int t = blk*blockDim.x + threadIdx.x; t < BMtot; t += nblk*blockDim.x) {
        int b = t / M; int m = t - b*M;
        const float* base = Y + ((size_t)(b*O + o)*3)*M + m;
        float v0 = base[0], v1 = base[M], v2 = base[2*(size_t)M];
        float nr = sqrtf(v0*v0 + v1*v1 + v2*v2) + EPSV;
        s += nr;
    }
    __shared__ float sh[256];
    sh[threadIdx.x] = s;
    __syncthreads();
    for (int st = 128; st > 0; st >>= 1) {
        if (threadIdx.x < st) sh[threadIdx.x] += sh[threadIdx.x+st];
        __syncthreads();
    }
    if (threadIdx.x == 0) part[(size_t)o*nblk + blk] = sh[0];
}

__global__ void bn_mean_final(const float* __restrict__ part, float* __restrict__ bn,
                              int O, int nblk, int cnt) {
    int o = blockIdx.x;
    __shared__ float s1[64];
    float a = 0.f;
    for (int t = threadIdx.x; t < nblk; t += 64) a += part[(size_t)o*nblk + t];
    s1[threadIdx.x] = a;
    __syncthreads();
    for (int st = 32; st > 0; st >>= 1) {
        if (threadIdx.x < st) s1[threadIdx.x] += s1[threadIdx.x+st];
        __syncthreads();
    }
    if (threadIdx.x == 0) bn[o] = s1[0] / (float)cnt;
}

__global__ void bn_var_partial(const float* __restrict__ Y, const float* __restrict__ bn,
                               int O, int M, int BMtot, int nblk, float* __restrict__ part) {
    int o = blockIdx.x, blk = blockIdx.y;
    float mean = bn[o];
    float s = 0.f;
    for (int t = blk*blockDim.x + threadIdx.x; t < BMtot; t += nblk*blockDim.x) {
        int b = t / M; int m = t - b*M;
        const float* base = Y + ((size_t)(b*O + o)*3)*M + m;
        float v0 = base[0], v1 = base[M], v2 = base[2*(size_t)M];
        float nr = sqrtf(v0*v0 + v1*v1 + v2*v2) + EPSV;
        float d = nr - mean;
        s += d*d;
    }
    __shared__ float sh[256];
    sh[threadIdx.x] = s;
    __syncthreads();
    for (int st = 128; st > 0; st >>= 1) {
        if (threadIdx.x < st) sh[threadIdx.x] += sh[threadIdx.x+st];
        __syncthreads();
    }
    if (threadIdx.x == 0) part[(size_t)o*nblk + blk] = sh[0];
}

__global__ void bn_var_final(const float* __restrict__ part, float* __restrict__ bn,
                             int O, int nblk, int cnt) {
    int o = blockIdx.x;
    __shared__ float s1[64];
    float a = 0.f;
    for (int t = threadIdx.x; t < nblk; t += 64) a += part[(size_t)o*nblk + t];
    s1[threadIdx.x] = a;
    __syncthreads();
    for (int st = 32; st > 0; st >>= 1) {
        if (threadIdx.x < st) s1[threadIdx.x] += s1[threadIdx.x+st];
        __syncthreads();
    }
    if (threadIdx.x == 0) {
        float var = s1[0] / (float)cnt;
        bn[O + o] = 1.f / sqrtf(var + BNEPS);
    }
}

// ---------------- BN apply (+ optional lrelu) ------------------------------------
__global__ void vn_combine(const float* __restrict__ P, const float* __restrict__ D,
                           const float* __restrict__ bn, float* __restrict__ Out,
                           int O, int M, int lrelu) {
    int total = BB*O*M;
    int t = blockIdx.x * blockDim.x + threadIdx.x;
    if (t >= total) return;
    int m = t % M; int r = t / M; int o = r % O; int b = r / O;
    size_t base = ((size_t)(b*O + o)*3)*M + m;
    float p0 = P[base], p1 = P[base + M], p2 = P[base + 2*(size_t)M];
    float nr = sqrtf(p0*p0 + p1*p1 + p2*p2) + EPSV;
    float sc = (nr - bn[o]) * bn[O + o] / nr;
    p0 *= sc; p1 *= sc; p2 *= sc;
    if (lrelu) {
        float d0 = D[base], d1 = D[base + M], d2 = D[base + 2*(size_t)M];
        float dot = p0*d0 + p1*d1 + p2*d2;
        if (dot < 0.f) {
            float coef = dot / (d0*d0 + d1*d1 + d2*d2 + EPSV);
            p0 -= coef*d0; p1 -= coef*d1; p2 -= coef*d2;
        }
    }
    Out[base] = p0; Out[base + M] = p1; Out[base + 2*(size_t)M] = p2;
}

// ---------------- VN max-pool over N (fp64 keys) ---------------------------------
__global__ void pool_n_kernel(const float* __restrict__ S, const float* __restrict__ Dv,
                              float* __restrict__ Out) {
    int bc = blockIdx.x;
    const float* Sb = S  + (size_t)bc*3*NN;
    const float* Db = Dv + (size_t)bc*3*NN;
    double bestv = -1.0e300; int besti = NN;
    for (int n = threadIdx.x; n < NN; n += 256) {
        double dot = (double)Sb[n]*(double)Db[n]
                   + (double)Sb[NN+n]*(double)Db[NN+n]
                   + (double)Sb[2*NN+n]*(double)Db[2*NN+n];
        if (dot > bestv || (dot == bestv && n < besti)) { bestv = dot; besti = n; }
    }
    __shared__ double sv[256]; __shared__ int si[256];
    sv[threadIdx.x] = bestv; si[threadIdx.x] = besti;
    __syncthreads();
    for (int st = 128; st > 0; st >>= 1) {
        if (threadIdx.x < st) {
            if (sv[threadIdx.x+st] > sv[threadIdx.x] ||
                (sv[threadIdx.x+st] == sv[threadIdx.x] && si[threadIdx.x+st] < si[threadIdx.x])) {
                sv[threadIdx.x] = sv[threadIdx.x+st]; si[threadIdx.x] = si[threadIdx.x+st];
            }
        }
        __syncthreads();
    }
    if (threadIdx.x == 0) {
        int n = si[0];
        for (int v = 0; v < 3; v++) Out[(size_t)bc*3 + v] = Sb[(size_t)v*NN + n];
    }
}

// ---------------- mean over N ----------------------------------------------------
__global__ void mean_n_kernel(const float* __restrict__ X, float* __restrict__ Out) {
    int row = blockIdx.x;
    const float* Xr = X + (size_t)row*NN;
    double s = 0.0;
    for (int n = threadIdx.x; n < NN; n += 256) s += (double)Xr[n];
    __shared__ double sh[256];
    sh[threadIdx.x] = s;
    __syncthreads();
    for (int st = 128; st > 0; st >>= 1) {
        if (threadIdx.x < st) sh[threadIdx.x] += sh[threadIdx.x+st];
        __syncthreads();
    }
    if (threadIdx.x == 0) Out[row] = (float)(sh[0] / (double)NN);
}

// ---------------- concat builders ------------------------------------------------
__global__ void concat42_kernel(const float* __restrict__ H1, const float* __restrict__ T3,
                                float* __restrict__ Out) {
    const int total = BB*42*3*NN;
    int t = blockIdx.x * blockDim.x + threadIdx.x;
    if (t >= total) return;
    int m = t % NN; int r = t / NN; int v = r % 3; r /= 3; int c = r % 42; int b = r / 42;
    float val = (c < 21) ? H1[((size_t)(b*21 + c)*3 + v)*NN + m]
                         : T3[(size_t)(b*21 + (c-21))*3 + v];
    Out[t] = val;
}

__global__ void concat682_kernel(const float* __restrict__ C3, const float* __restrict__ Mn,
                                 float* __restrict__ Out) {
    const int total = BB*682*3*NN;
    int t = blockIdx.x * blockDim.x + threadIdx.x;
    if (t >= total) return;
    int m = t % NN; int r = t / NN; int v = r % 3; r /= 3; int c = r % 682; int b = r / 682;
    float val = (c < 341) ? C3[((size_t)(b*341 + c)*3 + v)*NN + m]
                          : Mn[(size_t)(b*341 + (c-341))*3 + v];
    Out[t] = val;
}

// ---------------- final projection + global max ---------------------------------
__global__ void final_max_kernel(const float* __restrict__ H, const float* __restrict__ Z,
                                 float* __restrict__ out) {
    int bi = blockIdx.x; int b = bi / 682; int i = bi - b*682;
    const float* Hb = H + ((size_t)(b*682 + i)*3)*NN;
    const float* Zb = Z + (size_t)b*9*NN;
    float m0 = -3.0e38f, m1 = -3.0e38f, m2 = -3.0e38f;
    for (int n = threadIdx.x; n < NN; n += 128) {
        float h0 = Hb[n], h1 = Hb[NN+n], h2 = Hb[2*NN+n];
        float s0 = h0*Zb[0*NN+n] + h1*Zb[3*NN+n] + h2*Zb[6*NN+n];
        float s1 = h0*Zb[1*NN+n] + h1*Zb[4*NN+n] + h2*Zb[7*NN+n];
        float s2 = h0*Zb[2*NN+n] + h1*Zb[5*NN+n] + h2*Zb[8*NN+n];
        m0 = fmaxf(m0, s0); m1 = fmaxf(m1, s1); m2 = fmaxf(m2, s2);
    }
    __shared__ float sm[3][128];
    sm[0][threadIdx.x] = m0; sm[1][threadIdx.x] = m1; sm[2][threadIdx.x] = m2;
    __syncthreads();
    for (int st = 64; st > 0; st >>= 1) {
        if (threadIdx.x < st) {
            sm[0][threadIdx.x] = fmaxf(sm[0][threadIdx.x], sm[0][threadIdx.x+st]);
            sm[1][threadIdx.x] = fmaxf(sm[1][threadIdx.x], sm[1][threadIdx.x+st]);
            sm[2][threadIdx.x] = fmaxf(sm[2][threadIdx.x], sm[2][threadIdx.x+st]);
        }
        __syncthreads();
    }
    if (threadIdx.x < 3) out[(size_t)b*2046 + i*3 + threadIdx.x] = sm[threadIdx.x][0];
}

// ---------------- host helpers ---------------------------------------------------
static inline int cdiv(int a, int b) { return (a + b - 1) / b; }
static float* symf(const void* s) { void* p = 0; cudaGetSymbolAddress(&p, s); return (float*)p; }

static void gemm_launch(const float* W, const float* X, float* Y, int O, int C, int J) {
    dim3 grid(cdiv(J, 64), cdiv(O, 64), BB);
    gemm_vn<<<grid, 256>>>(W, X, Y, O, C, J);
}

static void gemm2_launch(const float* Wf, const float* Wd, const float* X,
                         float* P, float* D, int O, int C, int J) {
    dim3 grid(cdiv(J, 64), cdiv(O, 64), BB);
    gemm_vn2<<<grid, 256>>>(Wf, Wd, X, P, D, O, C, J);
}

static void bn_launch(const float* Y, int O, int M, float* partf, float* bn) {
    int BMtot = BB * M;
    int nblk = BMtot / 8192; if (nblk < 1) nblk = 1; if (nblk > 64) nblk = 64;
    bn_mean_partial<<<dim3(O, nblk), 256>>>(Y, O, M, BMtot, nblk, partf);
    bn_mean_final<<<O, 64>>>(partf, bn, O, nblk, BMtot);
    bn_var_partial<<<dim3(O, nblk), 256>>>(Y, bn, O, M, BMtot, nblk, partf);
    bn_var_final<<<O, 64>>>(partf, bn, O, nblk, BMtot);
}

static void combine_launch(const float* P, const float* D, const float* bn,
                           float* Out, int O, int M, int lrelu) {
    int total = BB * O * M;
    vn_combine<<<cdiv(total, 256), 256>>>(P, D, bn, Out, O, M, lrelu);
}

static void lrelu_stage(const float* Wf, const float* Wd, const float* X, float* outb,
                        int O, int C, int M, float* bufP, float* bufD,
                        float* partf, float* bn) {
    gemm2_launch(Wf, Wd, X, bufP, bufD, O, C, 3*M);
    bn_launch(bufP, O, M, partf, bn);
    combine_launch(bufP, bufD, bn, outb, O, M, 1);
}

extern "C" void kernel_launch(void* const* d_in, const int* in_sizes, int n_in,
                              void* d_out, int out_size) {
    const float* x          = (const float*)d_in[0];
    const float* pos_Wf     = (const float*)d_in[1];
    const float* pos_Wd     = (const float*)d_in[2];
    const float* pool_Wd    = (const float*)d_in[3];
    const float* c1_Wf      = (const float*)d_in[4];
    const float* c1_Wd      = (const float*)d_in[5];
    const float* st1_Wf     = (const float*)d_in[6];
    const float* st1_Wd     = (const float*)d_in[7];
    const float* st2_Wf     = (const float*)d_in[8];
    const float* st2_Wd     = (const float*)d_in[9];
    const float* st3_Wf     = (const float*)d_in[10];
    const float* st3_Wd     = (const float*)d_in[11];
    const float* st_pool_Wd = (const float*)d_in[12];
    const float* stf1_Wf    = (const float*)d_in[13];
    const float* stf1_Wd    = (const float*)d_in[14];
    const float* stf2_Wf    = (const float*)d_in[15];
    const float* stf2_Wd    = (const float*)d_in[16];
    const float* stf3_W     = (const float*)d_in[17];
    const float* c2_Wf      = (const float*)d_in[18];
    const float* c2_Wd      = (const float*)d_in[19];
    const float* c3_W       = (const float*)d_in[20];
    const float* std1_Wf    = (const float*)d_in[21];
    const float* std1_Wd    = (const float*)d_in[22];
    const float* std2_Wf    = (const float*)d_in[23];
    const float* std2_Wd    = (const float*)d_in[24];
    const float* std_lin    = (const float*)d_in[25];

    float*  bufP  = symf(g_bufP);
    float*  bufD  = symf(g_bufD);
    int*    idxp; { void* p=0; cudaGetSymbolAddress(&p, g_idx); idxp = (int*)p; }
    float*  hbuf  = symf(g_h);
    float*  h1b   = symf(g_h1);
    float*  s1b   = symf(g_s1);
    float*  s2b   = symf(g_s2);
    float*  s3b   = symf(g_s3);
    float*  spb   = symf(g_sp);
    float*  t1b   = symf(g_t1);
    float*  t2b   = symf(g_t2);
    float*  t3b   = symf(g_t3);
    float*  h42b  = symf(g_h42);
    float*  h42c  = symf(g_h42b);
    float*  mn3   = symf(g_mean3);
    float*  h682b = symf(g_h682);
    float*  z1b   = symf(g_z1);
    float*  z0sc  = symf(g_z0s);
    float*  partf = symf(g_part);
    float*  bn    = symf(g_bn);
    float*  bnpos = symf(g_bnpos);
    double* partd; { void* p=0; cudaGetSymbolAddress(&p, g_partd); partd = (double*)p; }

    float* outf = (float*)d_out;
    const int OUT1 = BB*2046;
    const int OUTZ = BB*9*NN;
    float* z0dst = (out_size >= OUT1 + OUTZ) ? (outf + OUT1) : z0sc;

    // 1. kNN (fp64 keys)
    knn_kernel<<<dim3(NN/128, BB), 128>>>(x, idxp);

    // 2. stage 1: XLA-replica f32 values; stats fp64-accumulated over replica norms
    {
        int nblk = 64;
        bn_stats_pos<<<dim3(21, nblk), 256>>>(x, idxp, pos_Wf, nblk, 0, bnpos, partd);
        bn_pos_final<<<21, 64>>>(partd, bnpos, nblk, BB*NKK, 0);
        bn_stats_pos<<<dim3(21, nblk), 256>>>(x, idxp, pos_Wf, nblk, 1, bnpos, partd);
        bn_pos_final<<<21, 64>>>(partd, bnpos, nblk, BB*NKK, 1);
        pool_k_replica<<<BB*NN, 32>>>(x, idxp, pos_Wf, pos_Wd, bnpos, pool_Wd, hbuf);
    }

    // 3. conv1 + STN trunk
    lrelu_stage(c1_Wf,  c1_Wd,  hbuf, h1b, 21, 21, NN, bufP, bufD, partf, bn);
    lrelu_stage(st1_Wf, st1_Wd, h1b,  s1b, 21, 21, NN, bufP, bufD, partf, bn);
    lrelu_stage(st2_Wf, st2_Wd, s1b,  s2b, 42, 21, NN, bufP, bufD, partf, bn);
    lrelu_stage(st3_Wf, st3_Wd, s2b,  s3b, 341, 42, NN, bufP, bufD, partf, bn);

    // 4. STN pool over N
    gemm_launch(st_pool_Wd, s3b, bufD, 341, 341, 3*NN);
    pool_n_kernel<<<BB*341, 256>>>(s3b, bufD, spb);

    // 5. STN head (M = 1)
    lrelu_stage(stf1_Wf, stf1_Wd, spb, t1b, 170, 341, 1, bufP, bufD, partf, bn);
    lrelu_stage(stf2_Wf, stf2_Wd, t1b, t2b, 85, 170, 1, bufP, bufD, partf, bn);
    gemm_launch(stf3_W, t2b, t3b, 21, 85, 3);

    // 6. concat + conv2 + conv3(bn only)
    concat42_kernel<<<cdiv(BB*42*3*NN, 256), 256>>>(h1b, t3b, h42b);
    lrelu_stage(c2_Wf, c2_Wd, h42b, h42c, 42, 42, NN, bufP, bufD, partf, bn);
    gemm_launch(c3_W, h42c, bufP, 341, 42, 3*NN);
    bn_launch(bufP, 341, NN, partf, bn);
    combine_launch(bufP, bufD, bn, bufP, 341, NN, 0);

    // 7. mean over N + concat to 682
    mean_n_kernel<<<BB*341*3, 256>>>(bufP, mn3);
    concat682_kernel<<<cdiv(BB*682*3*NN, 256), 256>>>(bufP, mn3, h682b);

    // 8. VNStdFeature
    lrelu_stage(std1_Wf, std1_Wd, h682b, z1b, 341, 682, NN, bufP, bufD, partf, bn);
    lrelu_stage(std2_Wf, std2_Wd, z1b,  bufP, 170, 341, NN, bufP, bufD, partf, bn);
    gemm_launch(std_lin, bufP, z0dst, 3, 170, 3*NN);

    // 9. frame projection + global max
    final_max_kernel<<<BB*682, 128>>>(h682b, z0dst, outf);
}

// round 11
// speedup vs baseline: 1.8409x; 1.8409x over previous
#include <cuda_runtime.h>
#include <math.h>

// ---------------- problem constants ----------------
#define BB   8
#define NN   4096
#define KNB  20
#define NKK  (NN*KNB)
#define EPSV 1e-6f
#define BNEPS 1e-5f

// ---------------- static device scratch (allocation-free) ----------------
__device__ float  g_bufP[BB*341*3*NN];   // also reused for stage-1 norms (55MB < 134MB)
__device__ float  g_bufD[BB*341*3*NN];
__device__ int    g_idx [BB*NKK];
__device__ float  g_h   [BB*21*3*NN];
__device__ float  g_h1  [BB*21*3*NN];
__device__ float  g_s1  [BB*21*3*NN];
__device__ float  g_s2  [BB*42*3*NN];
__device__ float  g_s3  [BB*341*3*NN];
__device__ float  g_sp  [BB*341*3];
__device__ float  g_t1  [BB*170*3];
__device__ float  g_t2  [BB*85*3];
__device__ float  g_t3  [BB*21*3];
__device__ float  g_h42 [BB*42*3*NN];
__device__ float  g_h42b[BB*42*3*NN];
__device__ float  g_mean3[BB*341*3];
__device__ float  g_h682[BB*682*3*NN];
__device__ float  g_z1  [BB*341*3*NN];
__device__ float  g_z0s [BB*3*3*NN];
__device__ float  g_part[682*64];
__device__ float  g_bn  [682*2];
__device__ double g_partd[21*64];
__device__ float  g_bnpos[21*2];   // stage-1: [mean, denom=sqrt(var+eps)] as f32

// ---------------- kNN: fp64-truth keys (FROZEN — passing config) ----------------
__global__ void knn_kernel(const float* __restrict__ x, int* __restrict__ idxout) {
    __shared__ float sx0[NN], sx1[NN], sx2[NN];
    int b = blockIdx.y;
    for (int t = threadIdx.x; t < 3*NN; t += blockDim.x) {
        float v = x[(size_t)b*3*NN + t];
        int d = t / NN, n = t - d*NN;
        if (d == 0) sx0[n] = v; else if (d == 1) sx1[n] = v; else sx2[n] = v;
    }
    __syncthreads();
    int i = blockIdx.x * blockDim.x + threadIdx.x;
    double xi0 = (double)sx0[i], xi1 = (double)sx1[i], xi2 = (double)sx2[i];
    double xxi = xi0*xi0 + xi1*xi1 + xi2*xi2;

    double bv[KNB]; int bi[KNB];
    #pragma unroll
    for (int t = 0; t < KNB; t++) { bv[t] = -1.0e300; bi[t] = 0; }
    double minv = -1.0e300; int minp = 0;

    for (int j = 0; j < NN; j++) {
        double a0 = (double)sx0[j], a1 = (double)sx1[j], a2 = (double)sx2[j];
        double dot = xi0*a0 + xi1*a1 + xi2*a2;
        double pd  = 2.0*dot - xxi - (a0*a0 + a1*a1 + a2*a2);
        if (pd > minv) {
            bv[minp] = pd; bi[minp] = j;
            minv = bv[0]; minp = 0;
            #pragma unroll
            for (int t = 1; t < KNB; t++)
                if (bv[t] < minv) { minv = bv[t]; minp = t; }
        }
    }
    int* dst = idxout + ((size_t)b*NN + i)*KNB;
    #pragma unroll
    for (int t = 0; t < KNB; t++) dst[t] = bi[t];
}

// ---- XLA-replica f32 feature build (FROZEN) ------------------------------------
__device__ __forceinline__ void feat_f32(const float* __restrict__ xb, int n, int j,
                                         float* f) {
    float xi0 = xb[n],  xi1 = xb[NN + n],  xi2 = xb[2*NN + n];
    float xj0 = xb[j],  xj1 = xb[NN + j],  xj2 = xb[2*NN + j];
    f[0] = __fsub_rn(xj0, xi0); f[1] = __fsub_rn(xj1, xi1); f[2] = __fsub_rn(xj2, xi2);
    f[3] = xi0; f[4] = xi1; f[5] = xi2;
    f[6] = __fsub_rn(__fmul_rn(xj1, xi2), __fmul_rn(xj2, xi1));
    f[7] = __fsub_rn(__fmul_rn(xj2, xi0), __fmul_rn(xj0, xi2));
    f[8] = __fsub_rn(__fmul_rn(xj0, xi1), __fmul_rn(xj1, xi0));
}

__device__ __forceinline__ float dot3_fma(float w0, float w1, float w2,
                                          float f0, float f1, float f2) {
    float a = __fmul_rn(w0, f0);
    a = __fmaf_rn(w1, f1, a);
    a = __fmaf_rn(w2, f2, a);
    return a;
}

__device__ __forceinline__ float sum3_nofma(float a0, float b0, float a1, float b1,
                                            float a2, float b2) {
    return __fadd_rn(__fadd_rn(__fmul_rn(a0, b0), __fmul_rn(a1, b1)), __fmul_rn(a2, b2));
}

// ---- stage-1: materialize replica norms ONCE (feature computed once per elem) ---
__global__ void pos_norm_kernel(const float* __restrict__ x, const int* __restrict__ idx,
                                const float* __restrict__ Wf, float* __restrict__ norms) {
    const int total = BB*NKK;
    int t = blockIdx.x * blockDim.x + threadIdx.x;
    if (t >= total) return;
    int b = t / NKK, nk = t - (t / NKK)*NKK;
    int n = nk / KNB;
    int j = idx[(size_t)b*NKK + nk];
    const float* xb = x + (size_t)b*3*NN;
    float f[9]; feat_f32(xb, n, j, f);
    #pragma unroll 3
    for (int o = 0; o < 21; o++) {
        float w0 = __ldg(Wf + o*3), w1 = __ldg(Wf + o*3 + 1), w2 = __ldg(Wf + o*3 + 2);
        float p0 = dot3_fma(w0, w1, w2, f[0], f[3], f[6]);
        float p1 = dot3_fma(w0, w1, w2, f[1], f[4], f[7]);
        float p2 = dot3_fma(w0, w1, w2, f[2], f[5], f[8]);
        float nsq = sum3_nofma(p0, p0, p1, p1, p2, p2);
        float nr = __fadd_rn(__fsqrt_rn(nsq), EPSV);
        norms[(size_t)o*total + t] = nr;
    }
}

// stats passes: SAME accumulation order as r9 (bit-identical bnpos)
__global__ void bn_pos_mean(const float* __restrict__ norms, int nblk,
                            double* __restrict__ part) {
    int o = blockIdx.x, blk = blockIdx.y;
    const int total = BB*NKK;
    const float* No = norms + (size_t)o*total;
    double s = 0.0;
    for (int t = blk*blockDim.x + threadIdx.x; t < total; t += nblk*blockDim.x)
        s += (double)No[t];
    __shared__ double sh[256];
    sh[threadIdx.x] = s;
    __syncthreads();
    for (int st = 128; st > 0; st >>= 1) {
        if (threadIdx.x < st) sh[threadIdx.x] += sh[threadIdx.x+st];
        __syncthreads();
    }
    if (threadIdx.x == 0) part[(size_t)o*nblk + blk] = sh[0];
}

__global__ void bn_pos_var(const float* __restrict__ norms, const float* __restrict__ bnpos,
                           int nblk, double* __restrict__ part) {
    int o = blockIdx.x, blk = blockIdx.y;
    const int total = BB*NKK;
    const float* No = norms + (size_t)o*total;
    float mean = bnpos[o];
    double s = 0.0;
    for (int t = blk*blockDim.x + threadIdx.x; t < total; t += nblk*blockDim.x) {
        double d = (double)__fsub_rn(No[t], mean);
        s += d*d;
    }
    __shared__ double sh[256];
    sh[threadIdx.x] = s;
    __syncthreads();
    for (int st = 128; st > 0; st >>= 1) {
        if (threadIdx.x < st) sh[threadIdx.x] += sh[threadIdx.x+st];
        __syncthreads();
    }
    if (threadIdx.x == 0) part[(size_t)o*nblk + blk] = sh[0];
}

__global__ void bn_pos_final(const double* __restrict__ part, float* __restrict__ bnpos,
                             int nblk, int cnt, int pass) {
    int o = blockIdx.x;
    __shared__ double s1[64];
    double a = 0.0;
    for (int t = threadIdx.x; t < nblk; t += 64) a += part[(size_t)o*nblk + t];
    s1[threadIdx.x] = a;
    __syncthreads();
    for (int st = 32; st > 0; st >>= 1) {
        if (threadIdx.x < st) s1[threadIdx.x] += s1[threadIdx.x+st];
        __syncthreads();
    }
    if (threadIdx.x == 0) {
        if (pass == 0) bnpos[o] = (float)(s1[0] / cnt);
        else {
            float var = (float)(s1[0] / cnt);
            bnpos[21 + o] = __fsqrt_rn(__fadd_rn(var, BNEPS));
        }
    }
}

// ------- stage-1 replica pool (FROZEN arithmetic — passing config) --------------
__global__ void pool_k_replica(const float* __restrict__ x, const int* __restrict__ idx,
                               const float* __restrict__ Wf, const float* __restrict__ Wd,
                               const float* __restrict__ bnpos,
                               const float* __restrict__ poolWd,
                               float* __restrict__ OutH) {
    int bnid = blockIdx.x; int b = bnid / NN; int n = bnid - b*NN;
    __shared__ float hs[21][3][KNB];
    __shared__ float wpool[441];
    __shared__ float wf[63], wd[63], bns[42];
    int lane = threadIdx.x;
    for (int t = lane; t < 441; t += 32) wpool[t] = poolWd[t];
    for (int t = lane; t < 63; t += 32) { wf[t] = Wf[t]; wd[t] = Wd[t]; }
    for (int t = lane; t < 42; t += 32) bns[t] = bnpos[t];
    __syncthreads();

    if (lane < KNB) {
        int k = lane;
        int j = idx[(size_t)b*NKK + (size_t)n*KNB + k];
        const float* xb = x + (size_t)b*3*NN;
        float f[9]; feat_f32(xb, n, j, f);
        for (int o = 0; o < 21; o++) {
            float a0 = wf[o*3], a1 = wf[o*3+1], a2 = wf[o*3+2];
            float p0 = dot3_fma(a0, a1, a2, f[0], f[3], f[6]);
            float p1 = dot3_fma(a0, a1, a2, f[1], f[4], f[7]);
            float p2 = dot3_fma(a0, a1, a2, f[2], f[5], f[8]);
            float nsq = sum3_nofma(p0, p0, p1, p1, p2, p2);
            float nr = __fadd_rn(__fsqrt_rn(nsq), EPSV);
            float nbn = __fdiv_rn(__fsub_rn(nr, bns[o]), bns[21 + o]);
            float q0 = __fmul_rn(__fdiv_rn(p0, nr), nbn);
            float q1 = __fmul_rn(__fdiv_rn(p1, nr), nbn);
            float q2 = __fmul_rn(__fdiv_rn(p2, nr), nbn);
            float c0 = wd[o*3], c1 = wd[o*3+1], c2 = wd[o*3+2];
            float d0 = dot3_fma(c0, c1, c2, f[0], f[3], f[6]);
            float d1 = dot3_fma(c0, c1, c2, f[1], f[4], f[7]);
            float d2 = dot3_fma(c0, c1, c2, f[2], f[5], f[8]);
            float dotv = sum3_nofma(q0, d0, q1, d1, q2, d2);
            float dsq  = sum3_nofma(d0, d0, d1, d1, d2, d2);
            if (!(dotv >= 0.f)) {
                float coef = __fdiv_rn(dotv, __fadd_rn(dsq, EPSV));
                q0 = __fsub_rn(q0, __fmul_rn(coef, d0));
                q1 = __fsub_rn(q1, __fmul_rn(coef, d1));
                q2 = __fsub_rn(q2, __fmul_rn(coef, d2));
            }
            hs[o][0][k] = q0; hs[o][1][k] = q1; hs[o][2][k] = q2;
        }
    }
    __syncthreads();
    if (lane < 21) {
        int o = lane;
        float bestdot = -3.0e38f; int bestk = 0;
        for (int k = 0; k < KNB; k++) {
            float d0 = __fmul_rn(wpool[o*21], hs[0][0][k]);
            float d1 = __fmul_rn(wpool[o*21], hs[0][1][k]);
            float d2 = __fmul_rn(wpool[o*21], hs[0][2][k]);
            for (int c = 1; c < 21; c++) {
                float w = wpool[o*21 + c];
                d0 = __fmaf_rn(w, hs[c][0][k], d0);
                d1 = __fmaf_rn(w, hs[c][1][k], d1);
                d2 = __fmaf_rn(w, hs[c][2][k], d2);
            }
            float dotv = sum3_nofma(hs[o][0][k], d0, hs[o][1][k], d1, hs[o][2][k], d2);
            if (dotv > bestdot) { bestdot = dotv; bestk = k; }
        }
        #pragma unroll
        for (int v = 0; v < 3; v++)
            OutH[((size_t)(b*21 + o)*3 + v)*NN + n] = hs[o][v][bestk];
    }
}

// ---------------- channel GEMM: 128x64 tile, 8x4 micro --------------------------
__global__ __launch_bounds__(256) void gemm_vn(const float* __restrict__ W,
                                               const float* __restrict__ X,
                                               float* __restrict__ Y, int O, int C, int J) {
    const float* Xb = X + (size_t)blockIdx.z * C * J;
    float*       Yb = Y + (size_t)blockIdx.z * O * J;
    int row0 = blockIdx.y * 128;
    int col0 = blockIdx.x * 64;
    __shared__ float Ws[16][132];
    __shared__ float Xs[16][68];
    int tid = threadIdx.x;
    int tx = tid % 16, ty = tid / 16;
    float acc[8][4] = {};

    for (int k0 = 0; k0 < C; k0 += 16) {
        {   // W tile: 128 (o) x 16 (c), 8 per thread
            int c = tid % 16, r16 = tid / 16;
            #pragma unroll
            for (int q = 0; q < 8; q++) {
                int r = r16*8 + q; int o = row0 + r; int cc = k0 + c;
                Ws[c][r] = (o < O && cc < C) ? W[(size_t)o*C + cc] : 0.f;
            }
        }
        {   // X tile: 16 (c) x 64 (j)
            int jl = tid % 64, k4 = tid / 64;
            #pragma unroll
            for (int q = 0; q < 4; q++) {
                int kk = k4 + q*4; int cc = k0 + kk; int col = col0 + jl;
                Xs[kk][jl] = (cc < C && col < J) ? Xb[(size_t)cc*J + col] : 0.f;
            }
        }
        __syncthreads();
        #pragma unroll
        for (int kk = 0; kk < 16; kk++) {
            float wr[8], xr[4];
            #pragma unroll
            for (int q = 0; q < 8; q++) wr[q] = Ws[kk][ty*8+q];
            #pragma unroll
            for (int q = 0; q < 4; q++) xr[q] = Xs[kk][tx*4+q];
            #pragma unroll
            for (int a = 0; a < 8; a++)
                #pragma unroll
                for (int bq = 0; bq < 4; bq++)
                    acc[a][bq] += wr[a]*xr[bq];
        }
        __syncthreads();
    }
    #pragma unroll
    for (int a = 0; a < 8; a++) {
        int o = row0 + ty*8 + a;
        if (o < O) {
            #pragma unroll
            for (int bq = 0; bq < 4; bq++) {
                int col = col0 + tx*4 + bq;
                if (col < J) Yb[(size_t)o*J + col] = acc[a][bq];
            }
        }
    }
}

// ---------------- fused dual GEMM: 128x64 tile, 8x4 micro -----------------------
__global__ __launch_bounds__(256) void gemm_vn2(const float* __restrict__ Wf,
                                                const float* __restrict__ Wd,
                                                const float* __restrict__ X,
                                                float* __restrict__ P, float* __restrict__ D,
                                                int O, int C, int J) {
    const float* Xb = X + (size_t)blockIdx.z * C * J;
    float*       Pb = P + (size_t)blockIdx.z * O * J;
    float*       Db = D + (size_t)blockIdx.z * O * J;
    int row0 = blockIdx.y * 128;
    int col0 = blockIdx.x * 64;
    __shared__ float Wfs[16][132];
    __shared__ float Wds[16][132];
    __shared__ float Xs [16][68];
    int tid = threadIdx.x;
    int tx = tid % 16, ty = tid / 16;
    float accP[8][4] = {};
    float accD[8][4] = {};

    for (int k0 = 0; k0 < C; k0 += 16) {
        {   // weight tiles: 128 (o) x 16 (c), 8 per thread
            int c = tid % 16, r16 = tid / 16;
            #pragma unroll
            for (int q = 0; q < 8; q++) {
                int r = r16*8 + q; int o = row0 + r; int cc = k0 + c;
                bool ok = (o < O && cc < C);
                Wfs[c][r] = ok ? Wf[(size_t)o*C + cc] : 0.f;
                Wds[c][r] = ok ? Wd[(size_t)o*C + cc] : 0.f;
            }
        }
        {   // X tile: 16 (c) x 64 (j)
            int jl = tid % 64, k4 = tid / 64;
            #pragma unroll
            for (int q = 0; q < 4; q++) {
                int kk = k4 + q*4; int cc = k0 + kk; int col = col0 + jl;
                Xs[kk][jl] = (cc < C && col < J) ? Xb[(size_t)cc*J + col] : 0.f;
            }
        }
        __syncthreads();
        #pragma unroll
        for (int kk = 0; kk < 16; kk++) {
            float wfr[8], wdr[8], xr[4];
            #pragma unroll
            for (int q = 0; q < 8; q++) wfr[q] = Wfs[kk][ty*8+q];
            #pragma unroll
            for (int q = 0; q < 8; q++) wdr[q] = Wds[kk][ty*8+q];
            #pragma unroll
            for (int q = 0; q < 4; q++) xr[q]  = Xs[kk][tx*4+q];
            #pragma unroll
            for (int a = 0; a < 8; a++)
                #pragma unroll
                for (int bq = 0; bq < 4; bq++) {
                    accP[a][bq] += wfr[a]*xr[bq];
                    accD[a][bq] += wdr[a]*xr[bq];
                }
        }
        __syncthreads();
    }
    #pragma unroll
    for (int a = 0; a < 8; a++) {
        int o = row0 + ty*8 + a;
        if (o < O) {
            #pragma unroll
            for (int bq = 0; bq < 4; bq++) {
                int col = col0 + tx*4 + bq;
                if (col < J) {
                    Pb[(size_t)o*J + col] = accP[a][bq];
                    Db[(size_t)o*J + col] = accD[a][bq];
                }
            }
        }
    }
}

// ---------------- BN stats: two-pass f32 ----------------------------------------
__global__ void bn_mean_partial(const float* __restrict__ Y, int O, int M, int BMtot,
                                int nblk, float* __restrict__ part) {
    int o = blockIdx.x, blk = blockIdx.y;
    float s = 0.f;
    for (int t = blk*blockDim.x + threadIdx.x; t < BMtot; t += nblk*blockDim.x) {
        int b = t / M; int m = t - b*M;
        const float* base = Y + ((size_t)(b*O + o)*3)*M + m;
        float v0 = base[0], v1 = base[M], v2 = base[2*(size_t)M];
        float nr = sqrtf(v0*v0 + v1*v1 + v2*v2) + EPSV;
        s += nr;
    }
    __shared__ float sh[256];
    sh[threadIdx.x] = s;
    __syncthreads();
    for (int st = 128; st > 0; st >>= 1) {
        if (threadIdx.x < st) sh[threadIdx.x] += sh[threadIdx.x+st];
        __syncthreads();
    }
    if (threadIdx.x == 0) part[(size_t)o*nblk + blk] = sh[0];
}

__global__ void bn_mean_final(const float* __restrict__ part, float* __restrict__ bn,
                              int O, int nblk, int cnt) {
    int o = blockIdx.x;
    __shared__ float s1[64];
    float a = 0.f;
    for (int t = threadIdx.x; t < nblk; t += 64) a += part[(size_t)o*nblk + t];
    s1[threadIdx.x] = a;
    __syncthreads();
    for (int st = 32; st > 0; st >>= 1) {
        if (threadIdx.x < st) s1[threadIdx.x] += s1[threadIdx.x+st];
        __syncthreads();
    }
    if (threadIdx.x == 0) bn[o] = s1[0] / (float)cnt;
}

__global__ void bn_var_partial(const float* __restrict__ Y, const float* __restrict__ bn,
                               int O, int M, int BMtot, int nblk, float* __restrict__ part) {
    int o = blockIdx.x, blk = blockIdx.y;
    float mean = bn[o];
    float s = 0.f;
    for (int t = blk*blockDim.x + threadIdx.x; t < BMtot; t += nblk*blockDim.x) {
        int b = t / M; int m = t - b*M;
        const float* base = Y + ((size_t)(b*O + o)*3)*M + m;
        float v0 = base[0], v1 = base[M], v2 = base[2*(size_t)M];
        float nr = sqrtf(v0*v0 + v1*v1 + v2*v2) + EPSV;
        float d = nr - mean;
        s += d*d;
    }
    __shared__ float sh[256];
    sh[threadIdx.x] = s;
    __syncthreads();
    for (int st = 128; st > 0; st >>= 1) {
        if (threadIdx.x < st) sh[threadIdx.x] += sh[threadIdx.x+st];
        __syncthreads();
    }
    if (threadIdx.x == 0) part[(size_t)o*nblk + blk] = sh[0];
}

__global__ void bn_var_final(const float* __restrict__ part, float* __restrict__ bn,
                             int O, int nblk, int cnt) {
    int o = blockIdx.x;
    __shared__ float s1[64];
    float a = 0.f;
    for (int t = threadIdx.x; t < nblk; t += 64) a += part[(size_t)o*nblk + t];
    s1[threadIdx.x] = a;
    __syncthreads();
    for (int st = 32; st > 0; st >>= 1) {
        if (threadIdx.x < st) s1[threadIdx.x] += s1[threadIdx.x+st];
        __syncthreads();
    }
    if (threadIdx.x == 0) {
        float var = s1[0] / (float)cnt;
        bn[O + o] = 1.f / sqrtf(var + BNEPS);
    }
}

// ---------------- BN apply (+ optional lrelu) ------------------------------------
__global__ void vn_combine(const float* __restrict__ P, const float* __restrict__ D,
                           const float* __restrict__ bn, float* __restrict__ Out,
                           int O, int M, int lrelu) {
    int total = BB*O*M;
    int t = blockIdx.x * blockDim.x + threadIdx.x;
    if (t >= total) return;
    int m = t % M; int r = t / M; int o = r % O; int b = r / O;
    size_t base = ((size_t)(b*O + o)*3)*M + m;
    float p0 = P[base], p1 = P[base + M], p2 = P[base + 2*(size_t)M];
    float nr = sqrtf(p0*p0 + p1*p1 + p2*p2) + EPSV;
    float sc = (nr - bn[o]) * bn[O + o] / nr;
    p0 *= sc; p1 *= sc; p2 *= sc;
    if (lrelu) {
        float d0 = D[base], d1 = D[base + M], d2 = D[base + 2*(size_t)M];
        float dot = p0*d0 + p1*d1 + p2*d2;
        if (dot < 0.f) {
            float coef = dot / (d0*d0 + d1*d1 + d2*d2 + EPSV);
            p0 -= coef*d0; p1 -= coef*d1; p2 -= coef*d2;
        }
    }
    Out[base] = p0; Out[base + M] = p1; Out[base + 2*(size_t)M] = p2;
}

// ---------------- VN max-pool over N (fp64 keys) ---------------------------------
__global__ void pool_n_kernel(const float* __restrict__ S, const float* __restrict__ Dv,
                              float* __restrict__ Out) {
    int bc = blockIdx.x;
    const float* Sb = S  + (size_t)bc*3*NN;
    const float* Db = Dv + (size_t)bc*3*NN;
    double bestv = -1.0e300; int besti = NN;
    for (int n = threadIdx.x; n < NN; n += 256) {
        double dot = (double)Sb[n]*(double)Db[n]
                   + (double)Sb[NN+n]*(double)Db[NN+n]
                   + (double)Sb[2*NN+n]*(double)Db[2*NN+n];
        if (dot > bestv || (dot == bestv && n < besti)) { bestv = dot; besti = n; }
    }
    __shared__ double sv[256]; __shared__ int si[256];
    sv[threadIdx.x] = bestv; si[threadIdx.x] = besti;
    __syncthreads();
    for (int st = 128; st > 0; st >>= 1) {
        if (threadIdx.x < st) {
            if (sv[threadIdx.x+st] > sv[threadIdx.x] ||
                (sv[threadIdx.x+st] == sv[threadIdx.x] && si[threadIdx.x+st] < si[threadIdx.x])) {
                sv[threadIdx.x] = sv[threadIdx.x+st]; si[threadIdx.x] = si[threadIdx.x+st];
            }
        }
        __syncthreads();
    }
    if (threadIdx.x == 0) {
        int n = si[0];
        for (int v = 0; v < 3; v++) Out[(size_t)bc*3 + v] = Sb[(size_t)v*NN + n];
    }
}

// ---------------- mean over N ----------------------------------------------------
__global__ void mean_n_kernel(const float* __restrict__ X, float* __restrict__ Out) {
    int row = blockIdx.x;
    const float* Xr = X + (size_t)row*NN;
    double s = 0.0;
    for (int n = threadIdx.x; n < NN; n += 256) s += (double)Xr[n];
    __shared__ double sh[256];
    sh[threadIdx.x] = s;
    __syncthreads();
    for (int st = 128; st > 0; st >>= 1) {
        if (threadIdx.x < st) sh[threadIdx.x] += sh[threadIdx.x+st];
        __syncthreads();
    }
    if (threadIdx.x == 0) Out[row] = (float)(sh[0] / (double)NN);
}

// ---------------- concat builders ------------------------------------------------
__global__ void concat42_kernel(const float* __restrict__ H1, const float* __restrict__ T3,
                                float* __restrict__ Out) {
    const int total = BB*42*3*NN;
    int t = blockIdx.x * blockDim.x + threadIdx.x;
    if (t >= total) return;
    int m = t % NN; int r = t / NN; int v = r % 3; r /= 3; int c = r % 42; int b = r / 42;
    float val = (c < 21) ? H1[((size_t)(b*21 + c)*3 + v)*NN + m]
                         : T3[(size_t)(b*21 + (c-21))*3 + v];
    Out[t] = val;
}

__global__ void concat682_kernel(const float* __restrict__ C3, const float* __restrict__ Mn,
                                 float* __restrict__ Out) {
    const int total = BB*682*3*NN;
    int t = blockIdx.x * blockDim.x + threadIdx.x;
    if (t >= total) return;
    int m = t % NN; int r = t / NN; int v = r % 3; r /= 3; int c = r % 682; int b = r / 682;
    float val = (c < 341) ? C3[((size_t)(b*341 + c)*3 + v)*NN + m]
                          : Mn[(size_t)(b*341 + (c-341))*3 + v];
    Out[t] = val;
}

// ---------------- final projection + global max ---------------------------------
__global__ void final_max_kernel(const float* __restrict__ H, const float* __restrict__ Z,
                                 float* __restrict__ out) {
    int bi = blockIdx.x; int b = bi / 682; int i = bi - b*682;
    const float* Hb = H + ((size_t)(b*682 + i)*3)*NN;
    const float* Zb = Z + (size_t)b*9*NN;
    float m0 = -3.0e38f, m1 = -3.0e38f, m2 = -3.0e38f;
    for (int n = threadIdx.x; n < NN; n += 128) {
        float h0 = Hb[n], h1 = Hb[NN+n], h2 = Hb[2*NN+n];
        float s0 = h0*Zb[0*NN+n] + h1*Zb[3*NN+n] + h2*Zb[6*NN+n];
        float s1 = h0*Zb[1*NN+n] + h1*Zb[4*NN+n] + h2*Zb[7*NN+n];
        float s2 = h0*Zb[2*NN+n] + h1*Zb[5*NN+n] + h2*Zb[8*NN+n];
        m0 = fmaxf(m0, s0); m1 = fmaxf(m1, s1); m2 = fmaxf(m2, s2);
    }
    __shared__ float sm[3][128];
    sm[0][threadIdx.x] = m0; sm[1][threadIdx.x] = m1; sm[2][threadIdx.x] = m2;
    __syncthreads();
    for (int st = 64; st > 0; st >>= 1) {
        if (threadIdx.x < st) {
            sm[0][threadIdx.x] = fmaxf(sm[0][threadIdx.x], sm[0][threadIdx.x+st]);
            sm[1][threadIdx.x] = fmaxf(sm[1][threadIdx.x], sm[1][threadIdx.x+st]);
            sm[2][threadIdx.x] = fmaxf(sm[2][threadIdx.x], sm[2][threadIdx.x+st]);
        }
        __syncthreads();
    }
    if (threadIdx.x < 3) out[(size_t)b*2046 + i*3 + threadIdx.x] = sm[threadIdx.x][0];
}

// ---------------- host helpers ---------------------------------------------------
static inline int cdiv(int a, int b) { return (a + b - 1) / b; }
static float* symf(const void* s) { void* p = 0; cudaGetSymbolAddress(&p, s); return (float*)p; }

static void gemm_launch(const float* W, const float* X, float* Y, int O, int C, int J) {
    dim3 grid(cdiv(J, 64), cdiv(O, 128), BB);
    gemm_vn<<<grid, 256>>>(W, X, Y, O, C, J);
}

static void gemm2_launch(const float* Wf, const float* Wd, const float* X,
                         float* P, float* D, int O, int C, int J) {
    dim3 grid(cdiv(J, 64), cdiv(O, 128), BB);
    gemm_vn2<<<grid, 256>>>(Wf, Wd, X, P, D, O, C, J);
}

static void bn_launch(const float* Y, int O, int M, float* partf, float* bn) {
    int BMtot = BB * M;
    int nblk = BMtot / 8192; if (nblk < 1) nblk = 1; if (nblk > 64) nblk = 64;
    bn_mean_partial<<<dim3(O, nblk), 256>>>(Y, O, M, BMtot, nblk, partf);
    bn_mean_final<<<O, 64>>>(partf, bn, O, nblk, BMtot);
    bn_var_partial<<<dim3(O, nblk), 256>>>(Y, bn, O, M, BMtot, nblk, partf);
    bn_var_final<<<O, 64>>>(partf, bn, O, nblk, BMtot);
}

static void combine_launch(const float* P, const float* D, const float* bn,
                           float* Out, int O, int M, int lrelu) {
    int total = BB * O * M;
    vn_combine<<<cdiv(total, 256), 256>>>(P, D, bn, Out, O, M, lrelu);
}

static void lrelu_stage(const float* Wf, const float* Wd, const float* X, float* outb,
                        int O, int C, int M, float* bufP, float* bufD,
                        float* partf, float* bn) {
    gemm2_launch(Wf, Wd, X, bufP, bufD, O, C, 3*M);
    bn_launch(bufP, O, M, partf, bn);
    combine_launch(bufP, bufD, bn, outb, O, M, 1);
}

extern "C" void kernel_launch(void* const* d_in, const int* in_sizes, int n_in,
                              void* d_out, int out_size) {
    const float* x          = (const float*)d_in[0];
    const float* pos_Wf     = (const float*)d_in[1];
    const float* pos_Wd     = (const float*)d_in[2];
    const float* pool_Wd    = (const float*)d_in[3];
    const float* c1_Wf      = (const float*)d_in[4];
    const float* c1_Wd      = (const float*)d_in[5];
    const float* st1_Wf     = (const float*)d_in[6];
    const float* st1_Wd     = (const float*)d_in[7];
    const float* st2_Wf     = (const float*)d_in[8];
    const float* st2_Wd     = (const float*)d_in[9];
    const float* st3_Wf     = (const float*)d_in[10];
    const float* st3_Wd     = (const float*)d_in[11];
    const float* st_pool_Wd = (const float*)d_in[12];
    const float* stf1_Wf    = (const float*)d_in[13];
    const float* stf1_Wd    = (const float*)d_in[14];
    const float* stf2_Wf    = (const float*)d_in[15];
    const float* stf2_Wd    = (const float*)d_in[16];
    const float* stf3_W     = (const float*)d_in[17];
    const float* c2_Wf      = (const float*)d_in[18];
    const float* c2_Wd      = (const float*)d_in[19];
    const float* c3_W       = (const float*)d_in[20];
    const float* std1_Wf    = (const float*)d_in[21];
    const float* std1_Wd    = (const float*)d_in[22];
    const float* std2_Wf    = (const float*)d_in[23];
    const float* std2_Wd    = (const float*)d_in[24];
    const float* std_lin    = (const float*)d_in[25];

    float*  bufP  = symf(g_bufP);
    float*  bufD  = symf(g_bufD);
    int*    idxp; { void* p=0; cudaGetSymbolAddress(&p, g_idx); idxp = (int*)p; }
    float*  hbuf  = symf(g_h);
    float*  h1b   = symf(g_h1);
    float*  s1b   = symf(g_s1);
    float*  s2b   = symf(g_s2);
    float*  s3b   = symf(g_s3);
    float*  spb   = symf(g_sp);
    float*  t1b   = symf(g_t1);
    float*  t2b   = symf(g_t2);
    float*  t3b   = symf(g_t3);
    float*  h42b  = symf(g_h42);
    float*  h42c  = symf(g_h42b);
    float*  mn3   = symf(g_mean3);
    float*  h682b = symf(g_h682);
    float*  z1b   = symf(g_z1);
    float*  z0sc  = symf(g_z0s);
    float*  partf = symf(g_part);
    float*  bn    = symf(g_bn);
    float*  bnpos = symf(g_bnpos);
    double* partd; { void* p=0; cudaGetSymbolAddress(&p, g_partd); partd = (double*)p; }

    float* outf = (float*)d_out;
    const int OUT1 = BB*2046;
    const int OUTZ = BB*9*NN;
    float* z0dst = (out_size >= OUT1 + OUTZ) ? (outf + OUT1) : z0sc;

    // 1. kNN (fp64 keys)
    knn_kernel<<<dim3(NN/128, BB), 128>>>(x, idxp);

    // 2. stage 1: materialize replica norms once, stats (bit-identical), fused pool
    {
        const int total = BB*NKK;
        const int nblk = 64;
        pos_norm_kernel<<<cdiv(total, 256), 256>>>(x, idxp, pos_Wf, bufP);
        bn_pos_mean<<<dim3(21, nblk), 256>>>(bufP, nblk, partd);
        bn_pos_final<<<21, 64>>>(partd, bnpos, nblk, total, 0);
        bn_pos_var<<<dim3(21, nblk), 256>>>(bufP, bnpos, nblk, partd);
        bn_pos_final<<<21, 64>>>(partd, bnpos, nblk, total, 1);
        pool_k_replica<<<BB*NN, 32>>>(x, idxp, pos_Wf, pos_Wd, bnpos, pool_Wd, hbuf);
    }

    // 3. conv1 + STN trunk
    lrelu_stage(c1_Wf,  c1_Wd,  hbuf, h1b, 21, 21, NN, bufP, bufD, partf, bn);
    lrelu_stage(st1_Wf, st1_Wd, h1b,  s1b, 21, 21, NN, bufP, bufD, partf, bn);
    lrelu_stage(st2_Wf, st2_Wd, s1b,  s2b, 42, 21, NN, bufP, bufD, partf, bn);
    lrelu_stage(st3_Wf, st3_Wd, s2b,  s3b, 341, 42, NN, bufP, bufD, partf, bn);

    // 4. STN pool over N
    gemm_launch(st_pool_Wd, s3b, bufD, 341, 341, 3*NN);
    pool_n_kernel<<<BB*341, 256>>>(s3b, bufD, spb);

    // 5. STN head (M = 1)
    lrelu_stage(stf1_Wf, stf1_Wd, spb, t1b, 170, 341, 1, bufP, bufD, partf, bn);
    lrelu_stage(stf2_Wf, stf2_Wd, t1b, t2b, 85, 170, 1, bufP, bufD, partf, bn);
    gemm_launch(stf3_W, t2b, t3b, 21, 85, 3);

    // 6. concat + conv2 + conv3(bn only)
    concat42_kernel<<<cdiv(BB*42*3*NN, 256), 256>>>(h1b, t3b, h42b);
    lrelu_stage(c2_Wf, c2_Wd, h42b, h42c, 42, 42, NN, bufP, bufD, partf, bn);
    gemm_launch(c3_W, h42c, bufP, 341, 42, 3*NN);
    bn_launch(bufP, 341, NN, partf, bn);
    combine_launch(bufP, bufD, bn, bufP, 341, NN, 0);

    // 7. mean over N + concat to 682
    mean_n_kernel<<<BB*341*3, 256>>>(bufP, mn3);
    concat682_kernel<<<cdiv(BB*682*3*NN, 256), 256>>>(bufP, mn3, h682b);

    // 8. VNStdFeature
    lrelu_stage(std1_Wf, std1_Wd, h682b, z1b, 341, 682, NN, bufP, bufD, partf, bn);
    lrelu_stage(std2_Wf, std2_Wd, z1b,  bufP, 170, 341, NN, bufP, bufD, partf, bn);
    gemm_launch(std_lin, bufP, z0dst, 3, 170, 3*NN);

    // 9. frame projection + global max
    final_max_kernel<<<BB*682, 128>>>(h682b, z0dst, outf);
}

// round 13
// speedup vs baseline: 2.6758x; 1.4536x over previous
#include <cuda_runtime.h>
#include <math.h>

// ---------------- problem constants ----------------
#define BB   8
#define NN   4096
#define KNB  20
#define NKK  (NN*KNB)
#define EPSV 1e-6f
#define BNEPS 1e-5f

// ---------------- static device scratch (allocation-free) ----------------
__device__ float  g_bufPD[(size_t)BB*682*3*NN];  // stacked P/D (268MB); also stage-1 norms
__device__ int    g_idx [BB*NKK];
__device__ float  g_h   [BB*21*3*NN];
__device__ float  g_h1  [BB*21*3*NN];
__device__ float  g_s1  [BB*21*3*NN];
__device__ float  g_s2  [BB*42*3*NN];
__device__ float  g_s3  [BB*341*3*NN];
__device__ float  g_sp  [BB*341*3];
__device__ float  g_t1  [BB*170*3];
__device__ float  g_t2  [BB*85*3];
__device__ float  g_t3  [BB*21*3];
__device__ float  g_h42 [BB*42*3*NN];
__device__ float  g_h42b[BB*42*3*NN];
__device__ float  g_mean3[BB*341*3];
__device__ float  g_h682[(size_t)BB*682*3*NN];
__device__ float  g_z1  [BB*341*3*NN];
__device__ float  g_z0s [BB*3*3*NN];
__device__ double g_part2[682*64*2];
__device__ float  g_bn  [682*2];
__device__ double g_partd[21*64];
__device__ float  g_bnpos[21*2];
__device__ float  g_wstk[761604];     // stacked [Wf;Wd] for all dual stages

// stacked-weight offsets (floats)
#define OFF_C1   0
#define OFF_ST1  882
#define OFF_ST2  1764
#define OFF_ST3  3528
#define OFF_STF1 32172
#define OFF_STF2 148112
#define OFF_C2   177012
#define OFF_STD1 180540
#define OFF_STD2 645664

__global__ void stack_w(const float* __restrict__ Wf, const float* __restrict__ Wd,
                        float* __restrict__ dst, int OC) {
    int t = blockIdx.x * blockDim.x + threadIdx.x;
    if (t < OC) dst[t] = Wf[t];
    else if (t < 2*OC) dst[t] = Wd[t - OC];
}

// ---------------- kNN: f32 prefilter + fp64-truth refine (same selection) -------
__global__ void knn_kernel(const float* __restrict__ x, int* __restrict__ idxout) {
    __shared__ float sx0[NN], sx1[NN], sx2[NN];
    int b = blockIdx.y;
    for (int t = threadIdx.x; t < 3*NN; t += blockDim.x) {
        float v = x[(size_t)b*3*NN + t];
        int d = t / NN, n = t - d*NN;
        if (d == 0) sx0[n] = v; else if (d == 1) sx1[n] = v; else sx2[n] = v;
    }
    __syncthreads();
    int i = blockIdx.x * blockDim.x + threadIdx.x;
    float fxi0 = sx0[i], fxi1 = sx1[i], fxi2 = sx2[i];
    float fxx = fxi0*fxi0 + fxi1*fxi1 + fxi2*fxi2;

    // pass 1: f32 top-20 threshold (filter only; margin covers f32 error)
    float fv[KNB];
    #pragma unroll
    for (int t = 0; t < KNB; t++) fv[t] = -3.0e38f;
    float fmin = -3.0e38f; int fminp = 0;
    for (int j = 0; j < NN; j++) {
        float a0 = sx0[j], a1 = sx1[j], a2 = sx2[j];
        float dot = fxi0*a0 + fxi1*a1 + fxi2*a2;
        float pd  = 2.f*dot - fxx - (a0*a0 + a1*a1 + a2*a2);
        if (pd > fmin) {
            fv[fminp] = pd; fmin = fv[0]; fminp = 0;
            #pragma unroll
            for (int t = 1; t < KNB; t++)
                if (fv[t] < fmin) { fmin = fv[t]; fminp = t; }
        }
    }
    float thr = fmin - 1e-3f;

    // pass 2: fp64 keys on candidates only, frozen insertion semantics
    double xi0 = (double)fxi0, xi1 = (double)fxi1, xi2 = (double)fxi2;
    double xxi = xi0*xi0 + xi1*xi1 + xi2*xi2;
    double bv[KNB]; int bi[KNB];
    #pragma unroll
    for (int t = 0; t < KNB; t++) { bv[t] = -1.0e300; bi[t] = 0; }
    double minv = -1.0e300; int minp = 0;
    for (int j = 0; j < NN; j++) {
        float a0 = sx0[j], a1 = sx1[j], a2 = sx2[j];
        float dotf = fxi0*a0 + fxi1*a1 + fxi2*a2;
        float pdf  = 2.f*dotf - fxx - (a0*a0 + a1*a1 + a2*a2);
        if (pdf >= thr) {
            double d0 = (double)a0, d1 = (double)a1, d2 = (double)a2;
            double dot = xi0*d0 + xi1*d1 + xi2*d2;
            double pd  = 2.0*dot - xxi - (d0*d0 + d1*d1 + d2*d2);
            if (pd > minv) {
                bv[minp] = pd; bi[minp] = j;
                minv = bv[0]; minp = 0;
                #pragma unroll
                for (int t = 1; t < KNB; t++)
                    if (bv[t] < minv) { minv = bv[t]; minp = t; }
            }
        }
    }
    int* dst = idxout + ((size_t)b*NN + i)*KNB;
    #pragma unroll
    for (int t = 0; t < KNB; t++) dst[t] = bi[t];
}

// ---- XLA-replica f32 feature build (FROZEN) ------------------------------------
__device__ __forceinline__ void feat_f32(const float* __restrict__ xb, int n, int j,
                                         float* f) {
    float xi0 = xb[n],  xi1 = xb[NN + n],  xi2 = xb[2*NN + n];
    float xj0 = xb[j],  xj1 = xb[NN + j],  xj2 = xb[2*NN + j];
    f[0] = __fsub_rn(xj0, xi0); f[1] = __fsub_rn(xj1, xi1); f[2] = __fsub_rn(xj2, xi2);
    f[3] = xi0; f[4] = xi1; f[5] = xi2;
    f[6] = __fsub_rn(__fmul_rn(xj1, xi2), __fmul_rn(xj2, xi1));
    f[7] = __fsub_rn(__fmul_rn(xj2, xi0), __fmul_rn(xj0, xi2));
    f[8] = __fsub_rn(__fmul_rn(xj0, xi1), __fmul_rn(xj1, xi0));
}

__device__ __forceinline__ float dot3_fma(float w0, float w1, float w2,
                                          float f0, float f1, float f2) {
    float a = __fmul_rn(w0, f0);
    a = __fmaf_rn(w1, f1, a);
    a = __fmaf_rn(w2, f2, a);
    return a;
}

__device__ __forceinline__ float sum3_nofma(float a0, float b0, float a1, float b1,
                                            float a2, float b2) {
    return __fadd_rn(__fadd_rn(__fmul_rn(a0, b0), __fmul_rn(a1, b1)), __fmul_rn(a2, b2));
}

// ---- stage-1: materialize replica norms ONCE (FROZEN values) -------------------
__global__ void pos_norm_kernel(const float* __restrict__ x, const int* __restrict__ idx,
                                const float* __restrict__ Wf, float* __restrict__ norms) {
    const int total = BB*NKK;
    int t = blockIdx.x * blockDim.x + threadIdx.x;
    if (t >= total) return;
    int b = t / NKK, nk = t - (t / NKK)*NKK;
    int n = nk / KNB;
    int j = idx[(size_t)b*NKK + nk];
    const float* xb = x + (size_t)b*3*NN;
    float f[9]; feat_f32(xb, n, j, f);
    #pragma unroll 3
    for (int o = 0; o < 21; o++) {
        float w0 = __ldg(Wf + o*3), w1 = __ldg(Wf + o*3 + 1), w2 = __ldg(Wf + o*3 + 2);
        float p0 = dot3_fma(w0, w1, w2, f[0], f[3], f[6]);
        float p1 = dot3_fma(w0, w1, w2, f[1], f[4], f[7]);
        float p2 = dot3_fma(w0, w1, w2, f[2], f[5], f[8]);
        float nsq = sum3_nofma(p0, p0, p1, p1, p2, p2);
        float nr = __fadd_rn(__fsqrt_rn(nsq), EPSV);
        norms[(size_t)o*total + t] = nr;
    }
}

// stage-1 stats: FROZEN two-pass fp64-accumulate (bit-identical bnpos)
__global__ void bn_pos_mean(const float* __restrict__ norms, int nblk,
                            double* __restrict__ part) {
    int o = blockIdx.x, blk = blockIdx.y;
    const int total = BB*NKK;
    const float* No = norms + (size_t)o*total;
    double s = 0.0;
    for (int t = blk*blockDim.x + threadIdx.x; t < total; t += nblk*blockDim.x)
        s += (double)No[t];
    __shared__ double sh[256];
    sh[threadIdx.x] = s;
    __syncthreads();
    for (int st = 128; st > 0; st >>= 1) {
        if (threadIdx.x < st) sh[threadIdx.x] += sh[threadIdx.x+st];
        __syncthreads();
    }
    if (threadIdx.x == 0) part[(size_t)o*nblk + blk] = sh[0];
}

__global__ void bn_pos_var(const float* __restrict__ norms, const float* __restrict__ bnpos,
                           int nblk, double* __restrict__ part) {
    int o = blockIdx.x, blk = blockIdx.y;
    const int total = BB*NKK;
    const float* No = norms + (size_t)o*total;
    float mean = bnpos[o];
    double s = 0.0;
    for (int t = blk*blockDim.x + threadIdx.x; t < total; t += nblk*blockDim.x) {
        double d = (double)__fsub_rn(No[t], mean);
        s += d*d;
    }
    __shared__ double sh[256];
    sh[threadIdx.x] = s;
    __syncthreads();
    for (int st = 128; st > 0; st >>= 1) {
        if (threadIdx.x < st) sh[threadIdx.x] += sh[threadIdx.x+st];
        __syncthreads();
    }
    if (threadIdx.x == 0) part[(size_t)o*nblk + blk] = sh[0];
}

__global__ void bn_pos_final(const double* __restrict__ part, float* __restrict__ bnpos,
                             int nblk, int cnt, int pass) {
    int o = blockIdx.x;
    __shared__ double s1[64];
    double a = 0.0;
    for (int t = threadIdx.x; t < nblk; t += 64) a += part[(size_t)o*nblk + t];
    s1[threadIdx.x] = a;
    __syncthreads();
    for (int st = 32; st > 0; st >>= 1) {
        if (threadIdx.x < st) s1[threadIdx.x] += s1[threadIdx.x+st];
        __syncthreads();
    }
    if (threadIdx.x == 0) {
        if (pass == 0) bnpos[o] = (float)(s1[0] / cnt);
        else {
            float var = (float)(s1[0] / cnt);
            bnpos[21 + o] = __fsqrt_rn(__fadd_rn(var, BNEPS));
        }
    }
}

// ------- stage-1 replica pool: 4 warps/block, FROZEN per-lane arithmetic --------
__global__ void pool_k_replica(const float* __restrict__ x, const int* __restrict__ idx,
                               const float* __restrict__ Wf, const float* __restrict__ Wd,
                               const float* __restrict__ bnpos,
                               const float* __restrict__ poolWd,
                               float* __restrict__ OutH) {
    int warp = threadIdx.x / 32;
    int lane = threadIdx.x % 32;
    int bnid = blockIdx.x*4 + warp;
    int b = bnid / NN, n = bnid - b*NN;
    __shared__ float hs[4][21][3][KNB];
    __shared__ float wpool[441];
    __shared__ float wf[63], wd[63], bns[42];
    int tid = threadIdx.x;
    for (int t = tid; t < 441; t += blockDim.x) wpool[t] = poolWd[t];
    for (int t = tid; t < 63; t += blockDim.x) { wf[t] = Wf[t]; wd[t] = Wd[t]; }
    for (int t = tid; t < 42; t += blockDim.x) bns[t] = bnpos[t];
    __syncthreads();

    if (lane < KNB) {
        int k = lane;
        int j = idx[(size_t)b*NKK + (size_t)n*KNB + k];
        const float* xb = x + (size_t)b*3*NN;
        float f[9]; feat_f32(xb, n, j, f);
        for (int o = 0; o < 21; o++) {
            float a0 = wf[o*3], a1 = wf[o*3+1], a2 = wf[o*3+2];
            float p0 = dot3_fma(a0, a1, a2, f[0], f[3], f[6]);
            float p1 = dot3_fma(a0, a1, a2, f[1], f[4], f[7]);
            float p2 = dot3_fma(a0, a1, a2, f[2], f[5], f[8]);
            float nsq = sum3_nofma(p0, p0, p1, p1, p2, p2);
            float nr = __fadd_rn(__fsqrt_rn(nsq), EPSV);
            float nbn = __fdiv_rn(__fsub_rn(nr, bns[o]), bns[21 + o]);
            float q0 = __fmul_rn(__fdiv_rn(p0, nr), nbn);
            float q1 = __fmul_rn(__fdiv_rn(p1, nr), nbn);
            float q2 = __fmul_rn(__fdiv_rn(p2, nr), nbn);
            float c0 = wd[o*3], c1 = wd[o*3+1], c2 = wd[o*3+2];
            float d0 = dot3_fma(c0, c1, c2, f[0], f[3], f[6]);
            float d1 = dot3_fma(c0, c1, c2, f[1], f[4], f[7]);
            float d2 = dot3_fma(c0, c1, c2, f[2], f[5], f[8]);
            float dotv = sum3_nofma(q0, d0, q1, d1, q2, d2);
            float dsq  = sum3_nofma(d0, d0, d1, d1, d2, d2);
            if (!(dotv >= 0.f)) {
                float coef = __fdiv_rn(dotv, __fadd_rn(dsq, EPSV));
                q0 = __fsub_rn(q0, __fmul_rn(coef, d0));
                q1 = __fsub_rn(q1, __fmul_rn(coef, d1));
                q2 = __fsub_rn(q2, __fmul_rn(coef, d2));
            }
            hs[warp][o][0][k] = q0; hs[warp][o][1][k] = q1; hs[warp][o][2][k] = q2;
        }
    }
    __syncthreads();
    if (lane < 21) {
        int o = lane;
        float bestdot = -3.0e38f; int bestk = 0;
        for (int k = 0; k < KNB; k++) {
            float d0 = __fmul_rn(wpool[o*21], hs[warp][0][0][k]);
            float d1 = __fmul_rn(wpool[o*21], hs[warp][0][1][k]);
            float d2 = __fmul_rn(wpool[o*21], hs[warp][0][2][k]);
            for (int c = 1; c < 21; c++) {
                float w = wpool[o*21 + c];
                d0 = __fmaf_rn(w, hs[warp][c][0][k], d0);
                d1 = __fmaf_rn(w, hs[warp][c][1][k], d1);
                d2 = __fmaf_rn(w, hs[warp][c][2][k], d2);
            }
            float dotv = sum3_nofma(hs[warp][o][0][k], d0, hs[warp][o][1][k], d1,
                                    hs[warp][o][2][k], d2);
            if (dotv > bestdot) { bestdot = dotv; bestk = k; }
        }
        #pragma unroll
        for (int v = 0; v < 3; v++)
            OutH[((size_t)(b*21 + o)*3 + v)*NN + n] = hs[warp][o][v][bestk];
    }
}

// ---------------- channel GEMM: 128x128 tile, 8x8 micro -------------------------
__global__ __launch_bounds__(256) void gemm_vn8(const float* __restrict__ W,
                                                const float* __restrict__ X,
                                                float* __restrict__ Y, int O, int C, int J) {
    const float* Xb = X + (size_t)blockIdx.z * C * J;
    float*       Yb = Y + (size_t)blockIdx.z * O * J;
    int row0 = blockIdx.y * 128;
    int col0 = blockIdx.x * 128;
    __shared__ float Ws[16][132];
    __shared__ float Xs[16][132];
    int tid = threadIdx.x;
    int tx = tid % 16, ty = tid / 16;
    float acc[8][8] = {};

    for (int k0 = 0; k0 < C; k0 += 16) {
        {   // W tile: 128 (o) x 16 (c)
            int c = tid % 16, r8 = tid / 16;
            #pragma unroll
            for (int q = 0; q < 8; q++) {
                int r = r8*8 + q; int o = row0 + r; int cc = k0 + c;
                Ws[c][r] = (o < O && cc < C) ? W[(size_t)o*C + cc] : 0.f;
            }
        }
        {   // X tile: 16 (c) x 128 (j)
            int jl = tid % 128, kb = (tid / 128)*8;
            #pragma unroll
            for (int q = 0; q < 8; q++) {
                int kk = kb + q; int cc = k0 + kk; int col = col0 + jl;
                Xs[kk][jl] = (cc < C && col < J) ? Xb[(size_t)cc*J + col] : 0.f;
            }
        }
        __syncthreads();
        #pragma unroll
        for (int kk = 0; kk < 16; kk++) {
            float wr[8], xr[8];
            #pragma unroll
            for (int q = 0; q < 8; q++) wr[q] = Ws[kk][ty*8+q];
            #pragma unroll
            for (int q = 0; q < 8; q++) xr[q] = Xs[kk][tx*8+q];
            #pragma unroll
            for (int a = 0; a < 8; a++)
                #pragma unroll
                for (int bq = 0; bq < 8; bq++)
                    acc[a][bq] += wr[a]*xr[bq];
        }
        __syncthreads();
    }
    #pragma unroll
    for (int a = 0; a < 8; a++) {
        int o = row0 + ty*8 + a;
        if (o < O) {
            #pragma unroll
            for (int bq = 0; bq < 8; bq++) {
                int col = col0 + tx*8 + bq;
                if (col < J) Yb[(size_t)o*J + col] = acc[a][bq];
            }
        }
    }
}

// small-O GEMM: one thread per output, ascending-c serial (bit-identical order)
__global__ void gemm_small(const float* __restrict__ W, const float* __restrict__ X,
                           float* __restrict__ Y, int O, int C, int J) {
    size_t total = (size_t)BB*O*J;
    size_t t = (size_t)blockIdx.x * blockDim.x + threadIdx.x;
    if (t >= total) return;
    int col = t % J; size_t r = t / J; int o = r % O; int b = r / O;
    const float* Xb = X + (size_t)b*C*J + col;
    const float* Wo = W + (size_t)o*C;
    float acc = 0.f;
    for (int c = 0; c < C; c++) acc += Wo[c]*Xb[(size_t)c*J];
    Y[(size_t)b*O*J + (size_t)o*J + col] = acc;
}

// ---------------- downstream BN stats: single pass sum+sumsq (double acc) -------
__global__ void bn_stats2(const float* __restrict__ Y, int O, int M, size_t bstride,
                          int BMtot, int nblk, double* __restrict__ part) {
    int o = blockIdx.x, blk = blockIdx.y;
    double s = 0.0, s2 = 0.0;
    for (int t = blk*blockDim.x + threadIdx.x; t < BMtot; t += nblk*blockDim.x) {
        int b = t / M; int m = t - b*M;
        const float* base = Y + (size_t)b*bstride + ((size_t)o*3)*M + m;
        float v0 = base[0], v1 = base[M], v2 = base[2*(size_t)M];
        float nr = sqrtf(v0*v0 + v1*v1 + v2*v2) + EPSV;
        s += (double)nr; s2 += (double)nr*(double)nr;
    }
    __shared__ double sh1[256], sh2[256];
    sh1[threadIdx.x] = s; sh2[threadIdx.x] = s2;
    __syncthreads();
    for (int st = 128; st > 0; st >>= 1) {
        if (threadIdx.x < st) { sh1[threadIdx.x] += sh1[threadIdx.x+st]; sh2[threadIdx.x] += sh2[threadIdx.x+st]; }
        __syncthreads();
    }
    if (threadIdx.x == 0) {
        part[((size_t)o*nblk + blk)*2]     = sh1[0];
        part[((size_t)o*nblk + blk)*2 + 1] = sh2[0];
    }
}

__global__ void bn_final2(const double* __restrict__ part, float* __restrict__ bn,
                          int O, int nblk, int cnt) {
    int o = blockIdx.x;
    __shared__ double s1[64], s2[64];
    double a = 0.0, c = 0.0;
    for (int t = threadIdx.x; t < nblk; t += 64) {
        a += part[((size_t)o*nblk + t)*2];
        c += part[((size_t)o*nblk + t)*2 + 1];
    }
    s1[threadIdx.x] = a; s2[threadIdx.x] = c;
    __syncthreads();
    for (int st = 32; st > 0; st >>= 1) {
        if (threadIdx.x < st) { s1[threadIdx.x] += s1[threadIdx.x+st]; s2[threadIdx.x] += s2[threadIdx.x+st]; }
        __syncthreads();
    }
    if (threadIdx.x == 0) {
        double mean = s1[0] / cnt;
        double var  = s2[0] / cnt - mean*mean;
        bn[o]     = (float)mean;
        bn[O + o] = (float)(1.0 / sqrt(var + (double)BNEPS));
    }
}

// ---------------- BN apply (+ optional lrelu), strided P/D ----------------------
__global__ void vn_combine(const float* __restrict__ P, const float* __restrict__ D,
                           const float* __restrict__ bn, float* __restrict__ Out,
                           int O, int M, int lrelu, size_t bstride) {
    int total = BB*O*M;
    int t = blockIdx.x * blockDim.x + threadIdx.x;
    if (t >= total) return;
    int m = t % M; int r = t / M; int o = r % O; int b = r / O;
    size_t bin = (size_t)b*bstride + ((size_t)o*3)*M + m;
    size_t bout = ((size_t)(b*O + o)*3)*M + m;
    float p0 = P[bin], p1 = P[bin + M], p2 = P[bin + 2*(size_t)M];
    float nr = sqrtf(p0*p0 + p1*p1 + p2*p2) + EPSV;
    float sc = (nr - bn[o]) * bn[O + o] / nr;
    p0 *= sc; p1 *= sc; p2 *= sc;
    if (lrelu) {
        float d0 = D[bin], d1 = D[bin + M], d2 = D[bin + 2*(size_t)M];
        float dot = p0*d0 + p1*d1 + p2*d2;
        if (dot < 0.f) {
            float coef = dot / (d0*d0 + d1*d1 + d2*d2 + EPSV);
            p0 -= coef*d0; p1 -= coef*d1; p2 -= coef*d2;
        }
    }
    Out[bout] = p0; Out[bout + M] = p1; Out[bout + 2*(size_t)M] = p2;
}

// ---------------- VN max-pool over N (fp64 keys) ---------------------------------
__global__ void pool_n_kernel(const float* __restrict__ S, const float* __restrict__ Dv,
                              float* __restrict__ Out) {
    int bc = blockIdx.x;
    const float* Sb = S  + (size_t)bc*3*NN;
    const float* Db = Dv + (size_t)bc*3*NN;
    double bestv = -1.0e300; int besti = NN;
    for (int n = threadIdx.x; n < NN; n += 256) {
        double dot = (double)Sb[n]*(double)Db[n]
                   + (double)Sb[NN+n]*(double)Db[NN+n]
                   + (double)Sb[2*NN+n]*(double)Db[2*NN+n];
        if (dot > bestv || (dot == bestv && n < besti)) { bestv = dot; besti = n; }
    }
    __shared__ double sv[256]; __shared__ int si[256];
    sv[threadIdx.x] = bestv; si[threadIdx.x] = besti;
    __syncthreads();
    for (int st = 128; st > 0; st >>= 1) {
        if (threadIdx.x < st) {
            if (sv[threadIdx.x+st] > sv[threadIdx.x] ||
                (sv[threadIdx.x+st] == sv[threadIdx.x] && si[threadIdx.x+st] < si[threadIdx.x])) {
                sv[threadIdx.x] = sv[threadIdx.x+st]; si[threadIdx.x] = si[threadIdx.x+st];
            }
        }
        __syncthreads();
    }
    if (threadIdx.x == 0) {
        int n = si[0];
        for (int v = 0; v < 3; v++) Out[(size_t)bc*3 + v] = Sb[(size_t)v*NN + n];
    }
}

// ---------------- mean over N ----------------------------------------------------
__global__ void mean_n_kernel(const float* __restrict__ X, float* __restrict__ Out) {
    int row = blockIdx.x;
    const float* Xr = X + (size_t)row*NN;
    double s = 0.0;
    for (int n = threadIdx.x; n < NN; n += 256) s += (double)Xr[n];
    __shared__ double sh[256];
    sh[threadIdx.x] = s;
    __syncthreads();
    for (int st = 128; st > 0; st >>= 1) {
        if (threadIdx.x < st) sh[threadIdx.x] += sh[threadIdx.x+st];
        __syncthreads();
    }
    if (threadIdx.x == 0) Out[row] = (float)(sh[0] / (double)NN);
}

// ---------------- concat builders ------------------------------------------------
__global__ void concat42_kernel(const float* __restrict__ H1, const float* __restrict__ T3,
                                float* __restrict__ Out) {
    const int total = BB*42*3*NN;
    int t = blockIdx.x * blockDim.x + threadIdx.x;
    if (t >= total) return;
    int m = t % NN; int r = t / NN; int v = r % 3; r /= 3; int c = r % 42; int b = r / 42;
    float val = (c < 21) ? H1[((size_t)(b*21 + c)*3 + v)*NN + m]
                         : T3[(size_t)(b*21 + (c-21))*3 + v];
    Out[t] = val;
}

__global__ void concat682_kernel(const float* __restrict__ C3, const float* __restrict__ Mn,
                                 float* __restrict__ Out) {
    const size_t total = (size_t)BB*682*3*NN;
    size_t t = (size_t)blockIdx.x * blockDim.x + threadIdx.x;
    if (t >= total) return;
    int m = t % NN; size_t r = t / NN; int v = r % 3; r /= 3; int c = r % 682; int b = r / 682;
    float val = (c < 341) ? C3[((size_t)(b*341 + c)*3 + v)*NN + m]
                          : Mn[(size_t)(b*341 + (c-341))*3 + v];
    Out[t] = val;
}

// ---------------- final projection + global max ---------------------------------
__global__ void final_max_kernel(const float* __restrict__ H, const float* __restrict__ Z,
                                 float* __restrict__ out) {
    int bi = blockIdx.x; int b = bi / 682; int i = bi - b*682;
    const float* Hb = H + ((size_t)(b*682 + i)*3)*NN;
    const float* Zb = Z + (size_t)b*9*NN;
    float m0 = -3.0e38f, m1 = -3.0e38f, m2 = -3.0e38f;
    for (int n = threadIdx.x; n < NN; n += 128) {
        float h0 = Hb[n], h1 = Hb[NN+n], h2 = Hb[2*NN+n];
        float s0 = h0*Zb[0*NN+n] + h1*Zb[3*NN+n] + h2*Zb[6*NN+n];
        float s1 = h0*Zb[1*NN+n] + h1*Zb[4*NN+n] + h2*Zb[7*NN+n];
        float s2 = h0*Zb[2*NN+n] + h1*Zb[5*NN+n] + h2*Zb[8*NN+n];
        m0 = fmaxf(m0, s0); m1 = fmaxf(m1, s1); m2 = fmaxf(m2, s2);
    }
    __shared__ float sm[3][128];
    sm[0][threadIdx.x] = m0; sm[1][threadIdx.x] = m1; sm[2][threadIdx.x] = m2;
    __syncthreads();
    for (int st = 64; st > 0; st >>= 1) {
        if (threadIdx.x < st) {
            sm[0][threadIdx.x] = fmaxf(sm[0][threadIdx.x], sm[0][threadIdx.x+st]);
            sm[1][threadIdx.x] = fmaxf(sm[1][threadIdx.x], sm[1][threadIdx.x+st]);
            sm[2][threadIdx.x] = fmaxf(sm[2][threadIdx.x], sm[2][threadIdx.x+st]);
        }
        __syncthreads();
    }
    if (threadIdx.x < 3) out[(size_t)b*2046 + i*3 + threadIdx.x] = sm[threadIdx.x][0];
}

// ---------------- host helpers ---------------------------------------------------
static inline int cdiv(int a, int b) { return (a + b - 1) / b; }
static float* symf(const void* s) { void* p = 0; cudaGetSymbolAddress(&p, s); return (float*)p; }

static void gemm8_launch(const float* W, const float* X, float* Y, int O, int C, int J) {
    if (O <= 24) {
        size_t total = (size_t)BB*O*J;
        gemm_small<<<(int)((total + 255)/256), 256>>>(W, X, Y, O, C, J);
    } else {
        dim3 grid(cdiv(J, 128), cdiv(O, 128), BB);
        gemm_vn8<<<grid, 256>>>(W, X, Y, O, C, J);
    }
}

static void bn_launch2(const float* Y, int O, int M, size_t bstride,
                       double* part2, float* bn) {
    int BMtot = BB * M;
    int nblk = BMtot / 8192; if (nblk < 1) nblk = 1; if (nblk > 64) nblk = 64;
    bn_stats2<<<dim3(O, nblk), 256>>>(Y, O, M, bstride, BMtot, nblk, part2);
    bn_final2<<<O, 64>>>(part2, bn, O, nblk, BMtot);
}

static void combine_launch(const float* P, const float* D, const float* bn,
                           float* Out, int O, int M, int lrelu, size_t bstride) {
    int total = BB * O * M;
    vn_combine<<<cdiv(total, 256), 256>>>(P, D, bn, Out, O, M, lrelu, bstride);
}

static void lrelu_stage2(const float* Wstk, const float* X, float* outb,
                         int O, int C, int M, float* bufPD,
                         double* part2, float* bn) {
    int J = 3*M;
    gemm8_launch(Wstk, X, bufPD, 2*O, C, J);
    size_t bs = (size_t)2*O*3*M;
    bn_launch2(bufPD, O, M, bs, part2, bn);
    combine_launch(bufPD, bufPD + (size_t)O*3*M, bn, outb, O, M, 1, bs);
}

extern "C" void kernel_launch(void* const* d_in, const int* in_sizes, int n_in,
                              void* d_out, int out_size) {
    const float* x          = (const float*)d_in[0];
    const float* pos_Wf     = (const float*)d_in[1];
    const float* pos_Wd     = (const float*)d_in[2];
    const float* pool_Wd    = (const float*)d_in[3];
    const float* c1_Wf      = (const float*)d_in[4];
    const float* c1_Wd      = (const float*)d_in[5];
    const float* st1_Wf     = (const float*)d_in[6];
    const float* st1_Wd     = (const float*)d_in[7];
    const float* st2_Wf     = (const float*)d_in[8];
    const float* st2_Wd     = (const float*)d_in[9];
    const float* st3_Wf     = (const float*)d_in[10];
    const float* st3_Wd     = (const float*)d_in[11];
    const float* st_pool_Wd = (const float*)d_in[12];
    const float* stf1_Wf    = (const float*)d_in[13];
    const float* stf1_Wd    = (const float*)d_in[14];
    const float* stf2_Wf    = (const float*)d_in[15];
    const float* stf2_Wd    = (const float*)d_in[16];
    const float* stf3_W     = (const float*)d_in[17];
    const float* c2_Wf      = (const float*)d_in[18];
    const float* c2_Wd      = (const float*)d_in[19];
    const float* c3_W       = (const float*)d_in[20];
    const float* std1_Wf    = (const float*)d_in[21];
    const float* std1_Wd    = (const float*)d_in[22];
    const float* std2_Wf    = (const float*)d_in[23];
    const float* std2_Wd    = (const float*)d_in[24];
    const float* std_lin    = (const float*)d_in[25];

    float*  bufPD = symf(g_bufPD);
    int*    idxp; { void* p=0; cudaGetSymbolAddress(&p, g_idx); idxp = (int*)p; }
    float*  hbuf  = symf(g_h);
    float*  h1b   = symf(g_h1);
    float*  s1b   = symf(g_s1);
    float*  s2b   = symf(g_s2);
    float*  s3b   = symf(g_s3);
    float*  spb   = symf(g_sp);
    float*  t1b   = symf(g_t1);
    float*  t2b   = symf(g_t2);
    float*  t3b   = symf(g_t3);
    float*  h42b  = symf(g_h42);
    float*  h42c  = symf(g_h42b);
    float*  mn3   = symf(g_mean3);
    float*  h682b = symf(g_h682);
    float*  z1b   = symf(g_z1);
    float*  z0sc  = symf(g_z0s);
    float*  bn    = symf(g_bn);
    float*  bnpos = symf(g_bnpos);
    float*  wstk  = symf(g_wstk);
    double* partd;  { void* p=0; cudaGetSymbolAddress(&p, g_partd);  partd  = (double*)p; }
    double* part2;  { void* p=0; cudaGetSymbolAddress(&p, g_part2);  part2  = (double*)p; }

    float* outf = (float*)d_out;
    const int OUT1 = BB*2046;
    const int OUTZ = BB*9*NN;
    float* z0dst = (out_size >= OUT1 + OUTZ) ? (outf + OUT1) : z0sc;

    // 0. stack dual weights [Wf;Wd]
    stack_w<<<cdiv(2*441, 256), 256>>>(c1_Wf,  c1_Wd,  wstk + OFF_C1,   441);
    stack_w<<<cdiv(2*441, 256), 256>>>(st1_Wf, st1_Wd, wstk + OFF_ST1,  441);
    stack_w<<<cdiv(2*882, 256), 256>>>(st2_Wf, st2_Wd, wstk + OFF_ST2,  882);
    stack_w<<<cdiv(2*14322, 256), 256>>>(st3_Wf, st3_Wd, wstk + OFF_ST3, 14322);
    stack_w<<<cdiv(2*57970, 256), 256>>>(stf1_Wf, stf1_Wd, wstk + OFF_STF1, 57970);
    stack_w<<<cdiv(2*14450, 256), 256>>>(stf2_Wf, stf2_Wd, wstk + OFF_STF2, 14450);
    stack_w<<<cdiv(2*1764, 256), 256>>>(c2_Wf,  c2_Wd,  wstk + OFF_C2,   1764);
    stack_w<<<cdiv(2*232562, 256), 256>>>(std1_Wf, std1_Wd, wstk + OFF_STD1, 232562);
    stack_w<<<cdiv(2*57970, 256), 256>>>(std2_Wf, std2_Wd, wstk + OFF_STD2, 57970);

    // 1. kNN (f32 prefilter + fp64 refine, same selection)
    knn_kernel<<<dim3(NN/128, BB), 128>>>(x, idxp);

    // 2. stage 1 (FROZEN values): norms once, two-pass stats, replica pool
    {
        const int total = BB*NKK;
        const int nblk = 64;
        pos_norm_kernel<<<cdiv(total, 256), 256>>>(x, idxp, pos_Wf, bufPD);
        bn_pos_mean<<<dim3(21, nblk), 256>>>(bufPD, nblk, partd);
        bn_pos_final<<<21, 64>>>(partd, bnpos, nblk, total, 0);
        bn_pos_var<<<dim3(21, nblk), 256>>>(bufPD, bnpos, nblk, partd);
        bn_pos_final<<<21, 64>>>(partd, bnpos, nblk, total, 1);
        pool_k_replica<<<BB*NN/4, 128>>>(x, idxp, pos_Wf, pos_Wd, bnpos, pool_Wd, hbuf);
    }

    // 3. conv1 + STN trunk (stacked dual gemms)
    lrelu_stage2(wstk + OFF_C1,  hbuf, h1b, 21, 21, NN, bufPD, part2, bn);
    lrelu_stage2(wstk + OFF_ST1, h1b,  s1b, 21, 21, NN, bufPD, part2, bn);
    lrelu_stage2(wstk + OFF_ST2, s1b,  s2b, 42, 21, NN, bufPD, part2, bn);
    lrelu_stage2(wstk + OFF_ST3, s2b,  s3b, 341, 42, NN, bufPD, part2, bn);

    // 4. STN pool over N
    gemm8_launch(st_pool_Wd, s3b, bufPD, 341, 341, 3*NN);
    pool_n_kernel<<<BB*341, 256>>>(s3b, bufPD, spb);

    // 5. STN head (M = 1)
    lrelu_stage2(wstk + OFF_STF1, spb, t1b, 170, 341, 1, bufPD, part2, bn);
    lrelu_stage2(wstk + OFF_STF2, t1b, t2b, 85, 170, 1, bufPD, part2, bn);
    gemm8_launch(stf3_W, t2b, t3b, 21, 85, 3);

    // 6. concat + conv2 + conv3(bn only)
    concat42_kernel<<<cdiv(BB*42*3*NN, 256), 256>>>(h1b, t3b, h42b);
    lrelu_stage2(wstk + OFF_C2, h42b, h42c, 42, 42, NN, bufPD, part2, bn);
    gemm8_launch(c3_W, h42c, bufPD, 341, 42, 3*NN);
    bn_launch2(bufPD, 341, NN, (size_t)341*3*NN, part2, bn);
    combine_launch(bufPD, bufPD, bn, bufPD, 341, NN, 0, (size_t)341*3*NN); // in place

    // 7. mean over N + concat to 682
    mean_n_kernel<<<BB*341*3, 256>>>(bufPD, mn3);
    {
        size_t total682 = (size_t)BB*682*3*NN;
        concat682_kernel<<<(int)((total682 + 255)/256), 256>>>(bufPD, mn3, h682b);
    }

    // 8. VNStdFeature
    lrelu_stage2(wstk + OFF_STD1, h682b, z1b, 341, 682, NN, bufPD, part2, bn);
    lrelu_stage2(wstk + OFF_STD2, z1b, s3b, 170, 341, NN, bufPD, part2, bn);
    gemm8_launch(std_lin, s3b, z0dst, 3, 170, 3*NN);

    // 9. frame projection + global max
    final_max_kernel<<<BB*682, 128>>>(h682b, z0dst, outf);
}

// round 14
// speedup vs baseline: 3.2849x; 1.2276x over previous
#include <cuda_runtime.h>
#include <math.h>

// ---------------- problem constants ----------------
#define BB   8
#define NN   4096
#define KNB  20
#define NKK  (NN*KNB)
#define EPSV 1e-6f
#define BNEPS 1e-5f

// ---------------- static device scratch (allocation-free) ----------------
__device__ float  g_bufPD[(size_t)BB*682*3*NN];  // stacked P/D (268MB); also stage-1 norms
__device__ int    g_idx [BB*NKK];
__device__ float  g_h   [BB*21*3*NN];
__device__ float  g_h1  [BB*21*3*NN];
__device__ float  g_s1  [BB*21*3*NN];
__device__ float  g_s2  [BB*42*3*NN];
__device__ float  g_s3  [BB*341*3*NN];
__device__ float  g_sp  [BB*341*3];
__device__ float  g_t1  [BB*170*3];
__device__ float  g_t2  [BB*85*3];
__device__ float  g_t3  [BB*21*3];
__device__ float  g_h42 [BB*42*3*NN];
__device__ float  g_h42b[BB*42*3*NN];
__device__ float  g_mean3[BB*341*3];
__device__ float  g_h682[(size_t)BB*682*3*NN];
__device__ float  g_z1  [BB*341*3*NN];
__device__ float  g_z0s [BB*3*3*NN];
__device__ double g_part2[682*64*2];
__device__ float  g_bn  [682*2];
__device__ double g_partd[21*64];
__device__ float  g_bnpos[21*2];
__device__ float  g_wstk[761604];     // stacked [Wf;Wd] for all dual stages

// stacked-weight offsets (floats)
#define OFF_C1   0
#define OFF_ST1  882
#define OFF_ST2  1764
#define OFF_ST3  3528
#define OFF_STF1 32172
#define OFF_STF2 148112
#define OFF_C2   177012
#define OFF_STD1 180540
#define OFF_STD2 645664

__global__ void stack_w(const float* __restrict__ Wf, const float* __restrict__ Wd,
                        float* __restrict__ dst, int OC) {
    int t = blockIdx.x * blockDim.x + threadIdx.x;
    if (t < OC) dst[t] = Wf[t];
    else if (t < 2*OC) dst[t] = Wd[t - OC];
}

// ---------------- kNN: f32 prefilter + fp64-truth refine (same selection) -------
__global__ void knn_kernel(const float* __restrict__ x, int* __restrict__ idxout) {
    __shared__ float sx0[NN], sx1[NN], sx2[NN];
    int b = blockIdx.y;
    for (int t = threadIdx.x; t < 3*NN; t += blockDim.x) {
        float v = x[(size_t)b*3*NN + t];
        int d = t / NN, n = t - d*NN;
        if (d == 0) sx0[n] = v; else if (d == 1) sx1[n] = v; else sx2[n] = v;
    }
    __syncthreads();
    int i = blockIdx.x * blockDim.x + threadIdx.x;
    float fxi0 = sx0[i], fxi1 = sx1[i], fxi2 = sx2[i];
    float fxx = fxi0*fxi0 + fxi1*fxi1 + fxi2*fxi2;

    float fv[KNB];
    #pragma unroll
    for (int t = 0; t < KNB; t++) fv[t] = -3.0e38f;
    float fmin = -3.0e38f; int fminp = 0;
    for (int j = 0; j < NN; j++) {
        float a0 = sx0[j], a1 = sx1[j], a2 = sx2[j];
        float dot = fxi0*a0 + fxi1*a1 + fxi2*a2;
        float pd  = 2.f*dot - fxx - (a0*a0 + a1*a1 + a2*a2);
        if (pd > fmin) {
            fv[fminp] = pd; fmin = fv[0]; fminp = 0;
            #pragma unroll
            for (int t = 1; t < KNB; t++)
                if (fv[t] < fmin) { fmin = fv[t]; fminp = t; }
        }
    }
    float thr = fmin - 1e-3f;

    double xi0 = (double)fxi0, xi1 = (double)fxi1, xi2 = (double)fxi2;
    double xxi = xi0*xi0 + xi1*xi1 + xi2*xi2;
    double bv[KNB]; int bi[KNB];
    #pragma unroll
    for (int t = 0; t < KNB; t++) { bv[t] = -1.0e300; bi[t] = 0; }
    double minv = -1.0e300; int minp = 0;
    for (int j = 0; j < NN; j++) {
        float a0 = sx0[j], a1 = sx1[j], a2 = sx2[j];
        float dotf = fxi0*a0 + fxi1*a1 + fxi2*a2;
        float pdf  = 2.f*dotf - fxx - (a0*a0 + a1*a1 + a2*a2);
        if (pdf >= thr) {
            double d0 = (double)a0, d1 = (double)a1, d2 = (double)a2;
            double dot = xi0*d0 + xi1*d1 + xi2*d2;
            double pd  = 2.0*dot - xxi - (d0*d0 + d1*d1 + d2*d2);
            if (pd > minv) {
                bv[minp] = pd; bi[minp] = j;
                minv = bv[0]; minp = 0;
                #pragma unroll
                for (int t = 1; t < KNB; t++)
                    if (bv[t] < minv) { minv = bv[t]; minp = t; }
            }
        }
    }
    int* dst = idxout + ((size_t)b*NN + i)*KNB;
    #pragma unroll
    for (int t = 0; t < KNB; t++) dst[t] = bi[t];
}

// ---- XLA-replica f32 feature build (FROZEN) ------------------------------------
__device__ __forceinline__ void feat_f32(const float* __restrict__ xb, int n, int j,
                                         float* f) {
    float xi0 = xb[n],  xi1 = xb[NN + n],  xi2 = xb[2*NN + n];
    float xj0 = xb[j],  xj1 = xb[NN + j],  xj2 = xb[2*NN + j];
    f[0] = __fsub_rn(xj0, xi0); f[1] = __fsub_rn(xj1, xi1); f[2] = __fsub_rn(xj2, xi2);
    f[3] = xi0; f[4] = xi1; f[5] = xi2;
    f[6] = __fsub_rn(__fmul_rn(xj1, xi2), __fmul_rn(xj2, xi1));
    f[7] = __fsub_rn(__fmul_rn(xj2, xi0), __fmul_rn(xj0, xi2));
    f[8] = __fsub_rn(__fmul_rn(xj0, xi1), __fmul_rn(xj1, xi0));
}

__device__ __forceinline__ float dot3_fma(float w0, float w1, float w2,
                                          float f0, float f1, float f2) {
    float a = __fmul_rn(w0, f0);
    a = __fmaf_rn(w1, f1, a);
    a = __fmaf_rn(w2, f2, a);
    return a;
}

__device__ __forceinline__ float sum3_nofma(float a0, float b0, float a1, float b1,
                                            float a2, float b2) {
    return __fadd_rn(__fadd_rn(__fmul_rn(a0, b0), __fmul_rn(a1, b1)), __fmul_rn(a2, b2));
}

// ---- stage-1: materialize replica norms ONCE (FROZEN values) -------------------
__global__ void pos_norm_kernel(const float* __restrict__ x, const int* __restrict__ idx,
                                const float* __restrict__ Wf, float* __restrict__ norms) {
    const int total = BB*NKK;
    int t = blockIdx.x * blockDim.x + threadIdx.x;
    if (t >= total) return;
    int b = t / NKK, nk = t - (t / NKK)*NKK;
    int n = nk / KNB;
    int j = idx[(size_t)b*NKK + nk];
    const float* xb = x + (size_t)b*3*NN;
    float f[9]; feat_f32(xb, n, j, f);
    #pragma unroll 3
    for (int o = 0; o < 21; o++) {
        float w0 = __ldg(Wf + o*3), w1 = __ldg(Wf + o*3 + 1), w2 = __ldg(Wf + o*3 + 2);
        float p0 = dot3_fma(w0, w1, w2, f[0], f[3], f[6]);
        float p1 = dot3_fma(w0, w1, w2, f[1], f[4], f[7]);
        float p2 = dot3_fma(w0, w1, w2, f[2], f[5], f[8]);
        float nsq = sum3_nofma(p0, p0, p1, p1, p2, p2);
        float nr = __fadd_rn(__fsqrt_rn(nsq), EPSV);
        norms[(size_t)o*total + t] = nr;
    }
}

// stage-1 stats: FROZEN two-pass fp64-accumulate (bit-identical bnpos)
__global__ void bn_pos_mean(const float* __restrict__ norms, int nblk,
                            double* __restrict__ part) {
    int o = blockIdx.x, blk = blockIdx.y;
    const int total = BB*NKK;
    const float* No = norms + (size_t)o*total;
    double s = 0.0;
    for (int t = blk*blockDim.x + threadIdx.x; t < total; t += nblk*blockDim.x)
        s += (double)No[t];
    __shared__ double sh[256];
    sh[threadIdx.x] = s;
    __syncthreads();
    for (int st = 128; st > 0; st >>= 1) {
        if (threadIdx.x < st) sh[threadIdx.x] += sh[threadIdx.x+st];
        __syncthreads();
    }
    if (threadIdx.x == 0) part[(size_t)o*nblk + blk] = sh[0];
}

__global__ void bn_pos_var(const float* __restrict__ norms, const float* __restrict__ bnpos,
                           int nblk, double* __restrict__ part) {
    int o = blockIdx.x, blk = blockIdx.y;
    const int total = BB*NKK;
    const float* No = norms + (size_t)o*total;
    float mean = bnpos[o];
    double s = 0.0;
    for (int t = blk*blockDim.x + threadIdx.x; t < total; t += nblk*blockDim.x) {
        double d = (double)__fsub_rn(No[t], mean);
        s += d*d;
    }
    __shared__ double sh[256];
    sh[threadIdx.x] = s;
    __syncthreads();
    for (int st = 128; st > 0; st >>= 1) {
        if (threadIdx.x < st) sh[threadIdx.x] += sh[threadIdx.x+st];
        __syncthreads();
    }
    if (threadIdx.x == 0) part[(size_t)o*nblk + blk] = sh[0];
}

__global__ void bn_pos_final(const double* __restrict__ part, float* __restrict__ bnpos,
                             int nblk, int cnt, int pass) {
    int o = blockIdx.x;
    __shared__ double s1[64];
    double a = 0.0;
    for (int t = threadIdx.x; t < nblk; t += 64) a += part[(size_t)o*nblk + t];
    s1[threadIdx.x] = a;
    __syncthreads();
    for (int st = 32; st > 0; st >>= 1) {
        if (threadIdx.x < st) s1[threadIdx.x] += s1[threadIdx.x+st];
        __syncthreads();
    }
    if (threadIdx.x == 0) {
        if (pass == 0) bnpos[o] = (float)(s1[0] / cnt);
        else {
            float var = (float)(s1[0] / cnt);
            bnpos[21 + o] = __fsqrt_rn(__fadd_rn(var, BNEPS));
        }
    }
}

// ------- stage-1 replica pool: 4 warps/block, FROZEN per-lane arithmetic --------
__global__ void pool_k_replica(const float* __restrict__ x, const int* __restrict__ idx,
                               const float* __restrict__ Wf, const float* __restrict__ Wd,
                               const float* __restrict__ bnpos,
                               const float* __restrict__ poolWd,
                               float* __restrict__ OutH) {
    int warp = threadIdx.x / 32;
    int lane = threadIdx.x % 32;
    int bnid = blockIdx.x*4 + warp;
    int b = bnid / NN, n = bnid - b*NN;
    __shared__ float hs[4][21][3][KNB];
    __shared__ float wpool[441];
    __shared__ float wf[63], wd[63], bns[42];
    int tid = threadIdx.x;
    for (int t = tid; t < 441; t += blockDim.x) wpool[t] = poolWd[t];
    for (int t = tid; t < 63; t += blockDim.x) { wf[t] = Wf[t]; wd[t] = Wd[t]; }
    for (int t = tid; t < 42; t += blockDim.x) bns[t] = bnpos[t];
    __syncthreads();

    if (lane < KNB) {
        int k = lane;
        int j = idx[(size_t)b*NKK + (size_t)n*KNB + k];
        const float* xb = x + (size_t)b*3*NN;
        float f[9]; feat_f32(xb, n, j, f);
        for (int o = 0; o < 21; o++) {
            float a0 = wf[o*3], a1 = wf[o*3+1], a2 = wf[o*3+2];
            float p0 = dot3_fma(a0, a1, a2, f[0], f[3], f[6]);
            float p1 = dot3_fma(a0, a1, a2, f[1], f[4], f[7]);
            float p2 = dot3_fma(a0, a1, a2, f[2], f[5], f[8]);
            float nsq = sum3_nofma(p0, p0, p1, p1, p2, p2);
            float nr = __fadd_rn(__fsqrt_rn(nsq), EPSV);
            float nbn = __fdiv_rn(__fsub_rn(nr, bns[o]), bns[21 + o]);
            float q0 = __fmul_rn(__fdiv_rn(p0, nr), nbn);
            float q1 = __fmul_rn(__fdiv_rn(p1, nr), nbn);
            float q2 = __fmul_rn(__fdiv_rn(p2, nr), nbn);
            float c0 = wd[o*3], c1 = wd[o*3+1], c2 = wd[o*3+2];
            float d0 = dot3_fma(c0, c1, c2, f[0], f[3], f[6]);
            float d1 = dot3_fma(c0, c1, c2, f[1], f[4], f[7]);
            float d2 = dot3_fma(c0, c1, c2, f[2], f[5], f[8]);
            float dotv = sum3_nofma(q0, d0, q1, d1, q2, d2);
            float dsq  = sum3_nofma(d0, d0, d1, d1, d2, d2);
            if (!(dotv >= 0.f)) {
                float coef = __fdiv_rn(dotv, __fadd_rn(dsq, EPSV));
                q0 = __fsub_rn(q0, __fmul_rn(coef, d0));
                q1 = __fsub_rn(q1, __fmul_rn(coef, d1));
                q2 = __fsub_rn(q2, __fmul_rn(coef, d2));
            }
            hs[warp][o][0][k] = q0; hs[warp][o][1][k] = q1; hs[warp][o][2][k] = q2;
        }
    }
    __syncthreads();
    if (lane < 21) {
        int o = lane;
        float bestdot = -3.0e38f; int bestk = 0;
        for (int k = 0; k < KNB; k++) {
            float d0 = __fmul_rn(wpool[o*21], hs[warp][0][0][k]);
            float d1 = __fmul_rn(wpool[o*21], hs[warp][0][1][k]);
            float d2 = __fmul_rn(wpool[o*21], hs[warp][0][2][k]);
            for (int c = 1; c < 21; c++) {
                float w = wpool[o*21 + c];
                d0 = __fmaf_rn(w, hs[warp][c][0][k], d0);
                d1 = __fmaf_rn(w, hs[warp][c][1][k], d1);
                d2 = __fmaf_rn(w, hs[warp][c][2][k], d2);
            }
            float dotv = sum3_nofma(hs[warp][o][0][k], d0, hs[warp][o][1][k], d1,
                                    hs[warp][o][2][k], d2);
            if (dotv > bestdot) { bestdot = dotv; bestk = k; }
        }
        #pragma unroll
        for (int v = 0; v < 3; v++)
            OutH[((size_t)(b*21 + o)*3 + v)*NN + n] = hs[warp][o][v][bestk];
    }
}

// ------ channel GEMM: 128x128 tile, conflict-free 2x2-quad micro, double-buffer --
// Requires J % 128 == 0 (enforced by launcher). Arithmetic per output element is
// identical to prior rounds (ascending k-tile, ascending kk, fma accumulate).
__global__ __launch_bounds__(256) void gemm_vn8(const float* __restrict__ W,
                                                const float* __restrict__ X,
                                                float* __restrict__ Y, int O, int C, int J) {
    const float* Xb = X + (size_t)blockIdx.z * C * J;
    float*       Yb = Y + (size_t)blockIdx.z * O * J;
    int row0 = blockIdx.y * 128;
    int col0 = blockIdx.x * 128;
    __shared__ __align__(16) float Ws[2][16][132];
    __shared__ __align__(16) float Xs[2][16][132];
    int tid = threadIdx.x;
    int tx = tid % 16, ty = tid / 16;
    int wc = tid % 16, wr8 = tid / 16;          // W-load role
    int xc = (tid % 32) * 4, xr = tid / 32;     // X-load role (warp-contiguous float4)
    float acc[8][8] = {};
    int nkt = (C + 15) / 16;

    float wreg[8];
    float4 xreg[2];
    // preload k-tile 0
    {
        #pragma unroll
        for (int q = 0; q < 8; q++) {
            int o = row0 + wr8*8 + q; int cc = wc;
            wreg[q] = (o < O && cc < C) ? W[(size_t)o*C + cc] : 0.f;
        }
        #pragma unroll
        for (int q = 0; q < 2; q++) {
            int cc = xr + q*8;
            xreg[q] = (cc < C) ? *(const float4*)(Xb + (size_t)cc*J + col0 + xc)
                               : make_float4(0.f, 0.f, 0.f, 0.f);
        }
        #pragma unroll
        for (int q = 0; q < 8; q++) Ws[0][wc][wr8*8 + q] = wreg[q];
        #pragma unroll
        for (int q = 0; q < 2; q++) *(float4*)&Xs[0][xr + q*8][xc] = xreg[q];
    }
    __syncthreads();

    for (int kt = 0; kt < nkt; kt++) {
        int cur = kt & 1;
        if (kt + 1 < nkt) {
            int k0 = (kt + 1) * 16;
            #pragma unroll
            for (int q = 0; q < 8; q++) {
                int o = row0 + wr8*8 + q; int cc = k0 + wc;
                wreg[q] = (o < O && cc < C) ? W[(size_t)o*C + cc] : 0.f;
            }
            #pragma unroll
            for (int q = 0; q < 2; q++) {
                int cc = k0 + xr + q*8;
                xreg[q] = (cc < C) ? *(const float4*)(Xb + (size_t)cc*J + col0 + xc)
                                   : make_float4(0.f, 0.f, 0.f, 0.f);
            }
        }
        #pragma unroll
        for (int kk = 0; kk < 16; kk++) {
            float4 wa = *(const float4*)&Ws[cur][kk][ty*4];
            float4 wb = *(const float4*)&Ws[cur][kk][64 + ty*4];
            float4 xa = *(const float4*)&Xs[cur][kk][tx*4];
            float4 xb4 = *(const float4*)&Xs[cur][kk][64 + tx*4];
            float wv[8] = {wa.x, wa.y, wa.z, wa.w, wb.x, wb.y, wb.z, wb.w};
            float xv[8] = {xa.x, xa.y, xa.z, xa.w, xb4.x, xb4.y, xb4.z, xb4.w};
            #pragma unroll
            for (int a = 0; a < 8; a++)
                #pragma unroll
                for (int bq = 0; bq < 8; bq++)
                    acc[a][bq] += wv[a]*xv[bq];
        }
        if (kt + 1 < nkt) {
            int nxt = (kt + 1) & 1;
            #pragma unroll
            for (int q = 0; q < 8; q++) Ws[nxt][wc][wr8*8 + q] = wreg[q];
            #pragma unroll
            for (int q = 0; q < 2; q++) *(float4*)&Xs[nxt][xr + q*8][xc] = xreg[q];
        }
        __syncthreads();
    }

    #pragma unroll
    for (int rg = 0; rg < 2; rg++) {
        #pragma unroll
        for (int q = 0; q < 4; q++) {
            int o = row0 + rg*64 + ty*4 + q;
            if (o < O) {
                #pragma unroll
                for (int cg = 0; cg < 2; cg++) {
                    int col = col0 + cg*64 + tx*4;
                    float4 v = make_float4(acc[rg*4+q][cg*4], acc[rg*4+q][cg*4+1],
                                           acc[rg*4+q][cg*4+2], acc[rg*4+q][cg*4+3]);
                    *(float4*)(Yb + (size_t)o*J + col) = v;
                }
            }
        }
    }
}

// small GEMM: one thread per output, ascending-c serial (bit-identical order)
__global__ void gemm_small(const float* __restrict__ W, const float* __restrict__ X,
                           float* __restrict__ Y, int O, int C, int J) {
    size_t total = (size_t)BB*O*J;
    size_t t = (size_t)blockIdx.x * blockDim.x + threadIdx.x;
    if (t >= total) return;
    int col = t % J; size_t r = t / J; int o = r % O; int b = r / O;
    const float* Xb = X + (size_t)b*C*J + col;
    const float* Wo = W + (size_t)o*C;
    float acc = 0.f;
    for (int c = 0; c < C; c++) acc += Wo[c]*Xb[(size_t)c*J];
    Y[(size_t)b*O*J + (size_t)o*J + col] = acc;
}

// ---------------- downstream BN stats: single pass sum+sumsq (double acc) -------
__global__ void bn_stats2(const float* __restrict__ Y, int O, int M, size_t bstride,
                          int BMtot, int nblk, double* __restrict__ part) {
    int o = blockIdx.x, blk = blockIdx.y;
    double s = 0.0, s2 = 0.0;
    for (int t = blk*blockDim.x + threadIdx.x; t < BMtot; t += nblk*blockDim.x) {
        int b = t / M; int m = t - b*M;
        const float* base = Y + (size_t)b*bstride + ((size_t)o*3)*M + m;
        float v0 = base[0], v1 = base[M], v2 = base[2*(size_t)M];
        float nr = sqrtf(v0*v0 + v1*v1 + v2*v2) + EPSV;
        s += (double)nr; s2 += (double)nr*(double)nr;
    }
    __shared__ double sh1[256], sh2[256];
    sh1[threadIdx.x] = s; sh2[threadIdx.x] = s2;
    __syncthreads();
    for (int st = 128; st > 0; st >>= 1) {
        if (threadIdx.x < st) { sh1[threadIdx.x] += sh1[threadIdx.x+st]; sh2[threadIdx.x] += sh2[threadIdx.x+st]; }
        __syncthreads();
    }
    if (threadIdx.x == 0) {
        part[((size_t)o*nblk + blk)*2]     = sh1[0];
        part[((size_t)o*nblk + blk)*2 + 1] = sh2[0];
    }
}

__global__ void bn_final2(const double* __restrict__ part, float* __restrict__ bn,
                          int O, int nblk, int cnt) {
    int o = blockIdx.x;
    __shared__ double s1[64], s2[64];
    double a = 0.0, c = 0.0;
    for (int t = threadIdx.x; t < nblk; t += 64) {
        a += part[((size_t)o*nblk + t)*2];
        c += part[((size_t)o*nblk + t)*2 + 1];
    }
    s1[threadIdx.x] = a; s2[threadIdx.x] = c;
    __syncthreads();
    for (int st = 32; st > 0; st >>= 1) {
        if (threadIdx.x < st) { s1[threadIdx.x] += s1[threadIdx.x+st]; s2[threadIdx.x] += s2[threadIdx.x+st]; }
        __syncthreads();
    }
    if (threadIdx.x == 0) {
        double mean = s1[0] / cnt;
        double var  = s2[0] / cnt - mean*mean;
        bn[o]     = (float)mean;
        bn[O + o] = (float)(1.0 / sqrt(var + (double)BNEPS));
    }
}

// ---------------- BN apply (+ optional lrelu), strided P/D ----------------------
__global__ void vn_combine(const float* __restrict__ P, const float* __restrict__ D,
                           const float* __restrict__ bn, float* __restrict__ Out,
                           int O, int M, int lrelu, size_t bstride) {
    int total = BB*O*M;
    int t = blockIdx.x * blockDim.x + threadIdx.x;
    if (t >= total) return;
    int m = t % M; int r = t / M; int o = r % O; int b = r / O;
    size_t bin = (size_t)b*bstride + ((size_t)o*3)*M + m;
    size_t bout = ((size_t)(b*O + o)*3)*M + m;
    float p0 = P[bin], p1 = P[bin + M], p2 = P[bin + 2*(size_t)M];
    float nr = sqrtf(p0*p0 + p1*p1 + p2*p2) + EPSV;
    float sc = (nr - bn[o]) * bn[O + o] / nr;
    p0 *= sc; p1 *= sc; p2 *= sc;
    if (lrelu) {
        float d0 = D[bin], d1 = D[bin + M], d2 = D[bin + 2*(size_t)M];
        float dot = p0*d0 + p1*d1 + p2*d2;
        if (dot < 0.f) {
            float coef = dot / (d0*d0 + d1*d1 + d2*d2 + EPSV);
            p0 -= coef*d0; p1 -= coef*d1; p2 -= coef*d2;
        }
    }
    Out[bout] = p0; Out[bout + M] = p1; Out[bout + 2*(size_t)M] = p2;
}

// ---------------- VN max-pool over N (fp64 keys) ---------------------------------
__global__ void pool_n_kernel(const float* __restrict__ S, const float* __restrict__ Dv,
                              float* __restrict__ Out) {
    int bc = blockIdx.x;
    const float* Sb = S  + (size_t)bc*3*NN;
    const float* Db = Dv + (size_t)bc*3*NN;
    double bestv = -1.0e300; int besti = NN;
    for (int n = threadIdx.x; n < NN; n += 256) {
        double dot = (double)Sb[n]*(double)Db[n]
                   + (double)Sb[NN+n]*(double)Db[NN+n]
                   + (double)Sb[2*NN+n]*(double)Db[2*NN+n];
        if (dot > bestv || (dot == bestv && n < besti)) { bestv = dot; besti = n; }
    }
    __shared__ double sv[256]; __shared__ int si[256];
    sv[threadIdx.x] = bestv; si[threadIdx.x] = besti;
    __syncthreads();
    for (int st = 128; st > 0; st >>= 1) {
        if (threadIdx.x < st) {
            if (sv[threadIdx.x+st] > sv[threadIdx.x] ||
                (sv[threadIdx.x+st] == sv[threadIdx.x] && si[threadIdx.x+st] < si[threadIdx.x])) {
                sv[threadIdx.x] = sv[threadIdx.x+st]; si[threadIdx.x] = si[threadIdx.x+st];
            }
        }
        __syncthreads();
    }
    if (threadIdx.x == 0) {
        int n = si[0];
        for (int v = 0; v < 3; v++) Out[(size_t)bc*3 + v] = Sb[(size_t)v*NN + n];
    }
}

// ---------------- mean over N ----------------------------------------------------
__global__ void mean_n_kernel(const float* __restrict__ X, float* __restrict__ Out) {
    int row = blockIdx.x;
    const float* Xr = X + (size_t)row*NN;
    double s = 0.0;
    for (int n = threadIdx.x; n < NN; n += 256) s += (double)Xr[n];
    __shared__ double sh[256];
    sh[threadIdx.x] = s;
    __syncthreads();
    for (int st = 128; st > 0; st >>= 1) {
        if (threadIdx.x < st) sh[threadIdx.x] += sh[threadIdx.x+st];
        __syncthreads();
    }
    if (threadIdx.x == 0) Out[row] = (float)(sh[0] / (double)NN);
}

// ---------------- concat builders ------------------------------------------------
__global__ void concat42_kernel(const float* __restrict__ H1, const float* __restrict__ T3,
                                float* __restrict__ Out) {
    const int total = BB*42*3*NN;
    int t = blockIdx.x * blockDim.x + threadIdx.x;
    if (t >= total) return;
    int m = t % NN; int r = t / NN; int v = r % 3; r /= 3; int c = r % 42; int b = r / 42;
    float val = (c < 21) ? H1[((size_t)(b*21 + c)*3 + v)*NN + m]
                         : T3[(size_t)(b*21 + (c-21))*3 + v];
    Out[t] = val;
}

__global__ void concat682_kernel(const float* __restrict__ C3, const float* __restrict__ Mn,
                                 float* __restrict__ Out) {
    const size_t total = (size_t)BB*682*3*NN;
    size_t t = (size_t)blockIdx.x * blockDim.x + threadIdx.x;
    if (t >= total) return;
    int m = t % NN; size_t r = t / NN; int v = r % 3; r /= 3; int c = r % 682; int b = r / 682;
    float val = (c < 341) ? C3[((size_t)(b*341 + c)*3 + v)*NN + m]
                          : Mn[(size_t)(b*341 + (c-341))*3 + v];
    Out[t] = val;
}

// ---------------- final projection + global max ---------------------------------
__global__ void final_max_kernel(const float* __restrict__ H, const float* __restrict__ Z,
                                 float* __restrict__ out) {
    int bi = blockIdx.x; int b = bi / 682; int i = bi - b*682;
    const float* Hb = H + ((size_t)(b*682 + i)*3)*NN;
    const float* Zb = Z + (size_t)b*9*NN;
    float m0 = -3.0e38f, m1 = -3.0e38f, m2 = -3.0e38f;
    for (int n = threadIdx.x; n < NN; n += 128) {
        float h0 = Hb[n], h1 = Hb[NN+n], h2 = Hb[2*NN+n];
        float s0 = h0*Zb[0*NN+n] + h1*Zb[3*NN+n] + h2*Zb[6*NN+n];
        float s1 = h0*Zb[1*NN+n] + h1*Zb[4*NN+n] + h2*Zb[7*NN+n];
        float s2 = h0*Zb[2*NN+n] + h1*Zb[5*NN+n] + h2*Zb[8*NN+n];
        m0 = fmaxf(m0, s0); m1 = fmaxf(m1, s1); m2 = fmaxf(m2, s2);
    }
    __shared__ float sm[3][128];
    sm[0][threadIdx.x] = m0; sm[1][threadIdx.x] = m1; sm[2][threadIdx.x] = m2;
    __syncthreads();
    for (int st = 64; st > 0; st >>= 1) {
        if (threadIdx.x < st) {
            sm[0][threadIdx.x] = fmaxf(sm[0][threadIdx.x], sm[0][threadIdx.x+st]);
            sm[1][threadIdx.x] = fmaxf(sm[1][threadIdx.x], sm[1][threadIdx.x+st]);
            sm[2][threadIdx.x] = fmaxf(sm[2][threadIdx.x], sm[2][threadIdx.x+st]);
        }
        __syncthreads();
    }
    if (threadIdx.x < 3) out[(size_t)b*2046 + i*3 + threadIdx.x] = sm[threadIdx.x][0];
}

// ---------------- host helpers ---------------------------------------------------
static inline int cdiv(int a, int b) { return (a + b - 1) / b; }
static float* symf(const void* s) { void* p = 0; cudaGetSymbolAddress(&p, s); return (float*)p; }

static void gemm8_launch(const float* W, const float* X, float* Y, int O, int C, int J) {
    if (O <= 24 || J < 128 || (J % 128) != 0) {
        size_t total = (size_t)BB*O*J;
        gemm_small<<<(int)((total + 255)/256), 256>>>(W, X, Y, O, C, J);
    } else {
        dim3 grid(J/128, cdiv(O, 128), BB);
        gemm_vn8<<<grid, 256>>>(W, X, Y, O, C, J);
    }
}

static void bn_launch2(const float* Y, int O, int M, size_t bstride,
                       double* part2, float* bn) {
    int BMtot = BB * M;
    int nblk = BMtot / 8192; if (nblk < 1) nblk = 1; if (nblk > 64) nblk = 64;
    bn_stats2<<<dim3(O, nblk), 256>>>(Y, O, M, bstride, BMtot, nblk, part2);
    bn_final2<<<O, 64>>>(part2, bn, O, nblk, BMtot);
}

static void combine_launch(const float* P, const float* D, const float* bn,
                           float* Out, int O, int M, int lrelu, size_t bstride) {
    int total = BB * O * M;
    vn_combine<<<cdiv(total, 256), 256>>>(P, D, bn, Out, O, M, lrelu, bstride);
}

static void lrelu_stage2(const float* Wstk, const float* X, float* outb,
                         int O, int C, int M, float* bufPD,
                         double* part2, float* bn) {
    int J = 3*M;
    gemm8_launch(Wstk, X, bufPD, 2*O, C, J);
    size_t bs = (size_t)2*O*3*M;
    bn_launch2(bufPD, O, M, bs, part2, bn);
    combine_launch(bufPD, bufPD + (size_t)O*3*M, bn, outb, O, M, 1, bs);
}

extern "C" void kernel_launch(void* const* d_in, const int* in_sizes, int n_in,
                              void* d_out, int out_size) {
    const float* x          = (const float*)d_in[0];
    const float* pos_Wf     = (const float*)d_in[1];
    const float* pos_Wd     = (const float*)d_in[2];
    const float* pool_Wd    = (const float*)d_in[3];
    const float* c1_Wf      = (const float*)d_in[4];
    const float* c1_Wd      = (const float*)d_in[5];
    const float* st1_Wf     = (const float*)d_in[6];
    const float* st1_Wd     = (const float*)d_in[7];
    const float* st2_Wf     = (const float*)d_in[8];
    const float* st2_Wd     = (const float*)d_in[9];
    const float* st3_Wf     = (const float*)d_in[10];
    const float* st3_Wd     = (const float*)d_in[11];
    const float* st_pool_Wd = (const float*)d_in[12];
    const float* stf1_Wf    = (const float*)d_in[13];
    const float* stf1_Wd    = (const float*)d_in[14];
    const float* stf2_Wf    = (const float*)d_in[15];
    const float* stf2_Wd    = (const float*)d_in[16];
    const float* stf3_W     = (const float*)d_in[17];
    const float* c2_Wf      = (const float*)d_in[18];
    const float* c2_Wd      = (const float*)d_in[19];
    const float* c3_W       = (const float*)d_in[20];
    const float* std1_Wf    = (const float*)d_in[21];
    const float* std1_Wd    = (const float*)d_in[22];
    const float* std2_Wf    = (const float*)d_in[23];
    const float* std2_Wd    = (const float*)d_in[24];
    const float* std_lin    = (const float*)d_in[25];

    float*  bufPD = symf(g_bufPD);
    int*    idxp; { void* p=0; cudaGetSymbolAddress(&p, g_idx); idxp = (int*)p; }
    float*  hbuf  = symf(g_h);
    float*  h1b   = symf(g_h1);
    float*  s1b   = symf(g_s1);
    float*  s2b   = symf(g_s2);
    float*  s3b   = symf(g_s3);
    float*  spb   = symf(g_sp);
    float*  t1b   = symf(g_t1);
    float*  t2b   = symf(g_t2);
    float*  t3b   = symf(g_t3);
    float*  h42b  = symf(g_h42);
    float*  h42c  = symf(g_h42b);
    float*  mn3   = symf(g_mean3);
    float*  h682b = symf(g_h682);
    float*  z1b   = symf(g_z1);
    float*  z0sc  = symf(g_z0s);
    float*  bn    = symf(g_bn);
    float*  bnpos = symf(g_bnpos);
    float*  wstk  = symf(g_wstk);
    double* partd;  { void* p=0; cudaGetSymbolAddress(&p, g_partd);  partd  = (double*)p; }
    double* part2;  { void* p=0; cudaGetSymbolAddress(&p, g_part2);  part2  = (double*)p; }

    float* outf = (float*)d_out;
    const int OUT1 = BB*2046;
    const int OUTZ = BB*9*NN;
    float* z0dst = (out_size >= OUT1 + OUTZ) ? (outf + OUT1) : z0sc;

    // 0. stack dual weights [Wf;Wd]
    stack_w<<<cdiv(2*441, 256), 256>>>(c1_Wf,  c1_Wd,  wstk + OFF_C1,   441);
    stack_w<<<cdiv(2*441, 256), 256>>>(st1_Wf, st1_Wd, wstk + OFF_ST1,  441);
    stack_w<<<cdiv(2*882, 256), 256>>>(st2_Wf, st2_Wd, wstk + OFF_ST2,  882);
    stack_w<<<cdiv(2*14322, 256), 256>>>(st3_Wf, st3_Wd, wstk + OFF_ST3, 14322);
    stack_w<<<cdiv(2*57970, 256), 256>>>(stf1_Wf, stf1_Wd, wstk + OFF_STF1, 57970);
    stack_w<<<cdiv(2*14450, 256), 256>>>(stf2_Wf, stf2_Wd, wstk + OFF_STF2, 14450);
    stack_w<<<cdiv(2*1764, 256), 256>>>(c2_Wf,  c2_Wd,  wstk + OFF_C2,   1764);
    stack_w<<<cdiv(2*232562, 256), 256>>>(std1_Wf, std1_Wd, wstk + OFF_STD1, 232562);
    stack_w<<<cdiv(2*57970, 256), 256>>>(std2_Wf, std2_Wd, wstk + OFF_STD2, 57970);

    // 1. kNN (f32 prefilter + fp64 refine, same selection)
    knn_kernel<<<dim3(NN/128, BB), 128>>>(x, idxp);

    // 2. stage 1 (FROZEN values): norms once, two-pass stats, replica pool
    {
        const int total = BB*NKK;
        const int nblk = 64;
        pos_norm_kernel<<<cdiv(total, 256), 256>>>(x, idxp, pos_Wf, bufPD);
        bn_pos_mean<<<dim3(21, nblk), 256>>>(bufPD, nblk, partd);
        bn_pos_final<<<21, 64>>>(partd, bnpos, nblk, total, 0);
        bn_pos_var<<<dim3(21, nblk), 256>>>(bufPD, bnpos, nblk, partd);
        bn_pos_final<<<21, 64>>>(partd, bnpos, nblk, total, 1);
        pool_k_replica<<<BB*NN/4, 128>>>(x, idxp, pos_Wf, pos_Wd, bnpos, pool_Wd, hbuf);
    }

    // 3. conv1 + STN trunk (stacked dual gemms)
    lrelu_stage2(wstk + OFF_C1,  hbuf, h1b, 21, 21, NN, bufPD, part2, bn);
    lrelu_stage2(wstk + OFF_ST1, h1b,  s1b, 21, 21, NN, bufPD, part2, bn);
    lrelu_stage2(wstk + OFF_ST2, s1b,  s2b, 42, 21, NN, bufPD, part2, bn);
    lrelu_stage2(wstk + OFF_ST3, s2b,  s3b, 341, 42, NN, bufPD, part2, bn);

    // 4. STN pool over N
    gemm8_launch(st_pool_Wd, s3b, bufPD, 341, 341, 3*NN);
    pool_n_kernel<<<BB*341, 256>>>(s3b, bufPD, spb);

    // 5. STN head (M = 1)
    lrelu_stage2(wstk + OFF_STF1, spb, t1b, 170, 341, 1, bufPD, part2, bn);
    lrelu_stage2(wstk + OFF_STF2, t1b, t2b, 85, 170, 1, bufPD, part2, bn);
    gemm8_launch(stf3_W, t2b, t3b, 21, 85, 3);

    // 6. concat + conv2 + conv3(bn only)
    concat42_kernel<<<cdiv(BB*42*3*NN, 256), 256>>>(h1b, t3b, h42b);
    lrelu_stage2(wstk + OFF_C2, h42b, h42c, 42, 42, NN, bufPD, part2, bn);
    gemm8_launch(c3_W, h42c, bufPD, 341, 42, 3*NN);
    bn_launch2(bufPD, 341, NN, (size_t)341*3*NN, part2, bn);
    combine_launch(bufPD, bufPD, bn, bufPD, 341, NN, 0, (size_t)341*3*NN); // in place

    // 7. mean over N + concat to 682
    mean_n_kernel<<<BB*341*3, 256>>>(bufPD, mn3);
    {
        size_t total682 = (size_t)BB*682*3*NN;
        concat682_kernel<<<(int)((total682 + 255)/256), 256>>>(bufPD, mn3, h682b);
    }

    // 8. VNStdFeature
    lrelu_stage2(wstk + OFF_STD1, h682b, z1b, 341, 682, NN, bufPD, part2, bn);
    lrelu_stage2(wstk + OFF_STD2, z1b, s3b, 170, 341, NN, bufPD, part2, bn);
    gemm8_launch(std_lin, s3b, z0dst, 3, 170, 3*NN);

    // 9. frame projection + global max
    final_max_kernel<<<BB*682, 128>>>(h682b, z0dst, outf);
}